// round 3
// baseline (speedup 1.0000x reference)
#include <cuda_runtime.h>
#include <cuda_bf16.h>
#include <math_constants.h>

// ---------------- problem constants ----------------
#define B      32
#define S      64
#define E      128
#define TSTEP  256
#define V      32000
#define ROWS   (B*TSTEP)          // 8192

// ---------------- scratch (device globals; no allocs allowed) ----------------
__device__ float g_scores[B * S * S];        // (b, s, t)
__device__ float g_xtran [B * S * S];        // (b, s, t)
__device__ float g_att0  [B * S];
__device__ float g_A     [B * TSTEP * S];    // att history (b, t, s)
__device__ float g_zs    [B * TSTEP * E];    // emitted states (row-major rows=b*256+t)

// ---------------- helpers ----------------
__device__ __forceinline__ void fma2(unsigned long long &d, unsigned long long a, unsigned long long b) {
    asm("fma.rn.f32x2 %0, %1, %2, %0;" : "+l"(d) : "l"(a), "l"(b));
}
__device__ __forceinline__ float lo32(unsigned long long v) { return __int_as_float((int)(unsigned)v); }
__device__ __forceinline__ float hi32(unsigned long long v) { return __int_as_float((int)(unsigned)(v >> 32)); }

// ================= Kernel A1: scores[b][s][t] = <xq_s, xk_t>/sqrt(E) =================
__global__ void kA1(const float* __restrict__ latent, const int* __restrict__ zi) {
    __shared__ float xkS[64 * 129];
    int b = blockIdx.x, tid = threadIdx.x;
    const float* xq = latent + (size_t)zi[(b >> 2)]      * 32768 + (size_t)(b & 3) * 8192;
    const float* xk = latent + (size_t)zi[8 + (b >> 2)]  * 32768 + (size_t)(b & 3) * 8192;
    for (int idx = tid; idx < 8192; idx += 256)
        xkS[(idx >> 7) * 129 + (idx & 127)] = __ldg(xk + idx);
    __syncthreads();
    int t = tid & 63, sg = tid >> 6;
    for (int i = 0; i < 16; i++) {
        int s = sg + 4 * i;
        float acc = 0.f;
        const float4* qp = (const float4*)(xq + s * 128);
        #pragma unroll 8
        for (int e4 = 0; e4 < 32; e4++) {
            float4 q = __ldg(qp + e4);
            const float* kp = &xkS[t * 129 + e4 * 4];
            acc += q.x * kp[0] + q.y * kp[1] + q.z * kp[2] + q.w * kp[3];
        }
        g_scores[b * 4096 + s * 64 + t] = acc * 0.08838834764831843f; // 1/sqrt(128)
    }
}

// ================= Kernel A2: column softmax -> xtran; att0 =================
__global__ void kA2(const float* __restrict__ latent, const int* __restrict__ zi) {
    int b = blockIdx.x, t = threadIdx.x; // 64 threads
    const float* col = g_scores + b * 4096 + t;
    float mx = -CUDART_INF_F;
    for (int s = 0; s < 64; s++) mx = fmaxf(mx, col[s * 64]);
    float sum = 0.f;
    for (int s = 0; s < 64; s++) {
        float e = __expf(col[s * 64] - mx);
        g_xtran[b * 4096 + s * 64 + t] = e;
        sum += e;
    }
    float inv = 1.f / sum;
    for (int s = 0; s < 64; s++) g_xtran[b * 4096 + s * 64 + t] *= inv;

    // att0 = softmax over s of xi[b][s][0]
    const float* ip = latent + (size_t)zi[24 + (b >> 2)] * 32768 + (size_t)(b & 3) * 8192;
    float xi = __ldg(ip + t * 128);
    __shared__ float smv[64];
    smv[t] = xi; __syncthreads();
    float m2 = -CUDART_INF_F;
    for (int s = 0; s < 64; s++) m2 = fmaxf(m2, smv[s]);
    float e2 = __expf(xi - m2);
    __syncthreads(); smv[t] = e2; __syncthreads();
    float su = 0.f;
    for (int s = 0; s < 64; s++) su += smv[s];
    g_att0[b * 64 + t] = e2 / su;
}

// ================= Kernel B: recurrence att_{t+1} = att_t @ xtran; zs = A @ xv ==========
__global__ __launch_bounds__(256) void kB(const float* __restrict__ latent, const int* __restrict__ zi) {
    __shared__ float xvS[64 * 128];
    __shared__ float attS[2][64];
    __shared__ float red[256];
    __shared__ float As[32 * 64];
    int b = blockIdx.x, tid = threadIdx.x;
    const float* xv = latent + (size_t)zi[16 + (b >> 2)] * 32768 + (size_t)(b & 3) * 8192;
    for (int idx = tid; idx < 8192; idx += 256) xvS[idx] = __ldg(xv + idx);

    int tp = tid & 63, c = tid >> 6;
    float xtc[16];
    #pragma unroll
    for (int i = 0; i < 16; i++) xtc[i] = g_xtran[b * 4096 + (c * 16 + i) * 64 + tp];
    if (tid < 64) attS[0][tid] = g_att0[b * 64 + tid];
    __syncthreads();

    int p = 0;
    for (int t = 0; t < 256; t++) {
        float partial = 0.f;
        #pragma unroll
        for (int i = 0; i < 16; i++) partial += attS[p][c * 16 + i] * xtc[i];
        red[tid] = partial;
        __syncthreads();
        if (c == 0) {
            g_A[(b * 256 + t) * 64 + tp] = attS[p][tp];
            attS[p ^ 1][tp] = red[tp] + red[64 + tp] + red[128 + tp] + red[192 + tp];
        }
        __syncthreads();
        p ^= 1;
    }

    // phase 2: zs[b][t][e] = sum_s A[t][s]*xv[s][e]
    int e = tid & 127, h = tid >> 7;
    for (int tb = 0; tb < 8; tb++) {
        __syncthreads();
        for (int k = tid; k < 2048; k += 256) As[k] = g_A[(b * 256 + tb * 32) * 64 + k];
        __syncthreads();
        for (int i = 0; i < 16; i++) {
            int tl = h * 16 + i;
            float acc = 0.f;
            #pragma unroll
            for (int s2 = 0; s2 < 64; s2++) acc += As[tl * 64 + s2] * xvS[s2 * 128 + e];
            g_zs[((size_t)b * 256 + tb * 32 + tl) * 128 + e] = acc;
        }
    }
}

// ================= Kernel C: fused logits GEMM + online logsumexp + gather ==============
// CTA: 32 rows x full vocab (chunks of 128). threads 256: tx=vocab lane, ty=row group(4 rows)
#define WPITCH 132
#define SMEM_C ((4096 + 16896 + 128) * 4)

__global__ __launch_bounds__(256, 2) void kC(const float* __restrict__ vw,
                                             const float* __restrict__ vb,
                                             const int*   __restrict__ y,
                                             float*       __restrict__ out) {
    extern __shared__ float sm[];
    float* zsS = sm;            // 32*128
    float* wS  = sm + 4096;     // 128*132
    float* bS  = wS + 16896;    // 128

    int tid = threadIdx.x;
    int tx = tid & 31, ty = tid >> 5;
    int rowbase = blockIdx.x * 32;

    // load zs tile (32 rows, contiguous)
    {
        const float4* zg = (const float4*)(g_zs + (size_t)rowbase * 128);
        float4* zd = (float4*)zsS;
        #pragma unroll
        for (int k = 0; k < 4; k++) zd[tid + 256 * k] = __ldg(zg + tid + 256 * k);
    }

    int   ytgt[4];
    float m[4], s[4], tg[4];
    #pragma unroll
    for (int j = 0; j < 4; j++) {
        ytgt[j] = __ldg(y + rowbase + ty * 4 + j);
        m[j] = -CUDART_INF_F; s[j] = 0.f; tg[j] = 0.f;
    }

    for (int cch = 0; cch < 250; cch++) {
        int vbase = cch * 128;
        __syncthreads();   // previous compute done before overwriting wS/bS; also first-iter zs fence
        // load vocab chunk: 128 rows into pitch-132 smem, fully coalesced
        const float4* wg = (const float4*)(vw + (size_t)vbase * 128);
        #pragma unroll
        for (int k = 0; k < 16; k++) {
            int idx = tid + 256 * k;
            int v = idx >> 5, f = idx & 31;
            float4 val = __ldg(wg + idx);
            *(float4*)&wS[v * WPITCH + f * 4] = val;
        }
        if (tid < 128) bS[tid] = __ldg(vb + vbase + tid);
        __syncthreads();

        unsigned long long acc[4][4];
        #pragma unroll
        for (int j = 0; j < 4; j++)
            #pragma unroll
            for (int jj = 0; jj < 4; jj++) acc[j][jj] = 0ULL;

        #pragma unroll 4
        for (int e4 = 0; e4 < 32; e4++) {
            ulonglong2 wq[4];
            #pragma unroll
            for (int jj = 0; jj < 4; jj++)
                wq[jj] = *(const ulonglong2*)&wS[(tx + 32 * jj) * WPITCH + e4 * 4];
            #pragma unroll
            for (int j = 0; j < 4; j++) {
                ulonglong2 zq = *(const ulonglong2*)&zsS[(ty * 4 + j) * 128 + e4 * 4];
                #pragma unroll
                for (int jj = 0; jj < 4; jj++) {
                    fma2(acc[j][jj], zq.x, wq[jj].x);
                    fma2(acc[j][jj], zq.y, wq[jj].y);
                }
            }
        }

        // epilogue: 4 complete logits per row -> online logsumexp + target capture
        #pragma unroll
        for (int j = 0; j < 4; j++) {
            float v0 = lo32(acc[j][0]) + hi32(acc[j][0]) + bS[tx];
            float v1 = lo32(acc[j][1]) + hi32(acc[j][1]) + bS[tx + 32];
            float v2 = lo32(acc[j][2]) + hi32(acc[j][2]) + bS[tx + 64];
            float v3 = lo32(acc[j][3]) + hi32(acc[j][3]) + bS[tx + 96];
            int vg = vbase + tx;
            tg[j] += (vg      == ytgt[j]) ? v0 : 0.f;
            tg[j] += (vg + 32 == ytgt[j]) ? v1 : 0.f;
            tg[j] += (vg + 64 == ytgt[j]) ? v2 : 0.f;
            tg[j] += (vg + 96 == ytgt[j]) ? v3 : 0.f;
            float ml = fmaxf(fmaxf(v0, v1), fmaxf(v2, v3));
            float mn = fmaxf(m[j], ml);
            s[j] = s[j] * __expf(m[j] - mn)
                 + __expf(v0 - mn) + __expf(v1 - mn) + __expf(v2 - mn) + __expf(v3 - mn);
            m[j] = mn;
        }
    }

    // warp reduce across 32 vocab lanes
    #pragma unroll
    for (int j = 0; j < 4; j++) {
        #pragma unroll
        for (int off = 16; off; off >>= 1) {
            float mo = __shfl_xor_sync(0xffffffffu, m[j],  off);
            float so = __shfl_xor_sync(0xffffffffu, s[j],  off);
            float to = __shfl_xor_sync(0xffffffffu, tg[j], off);
            float mn = fmaxf(m[j], mo);
            s[j] = s[j] * __expf(m[j] - mn) + so * __expf(mo - mn);
            m[j] = mn;
            tg[j] += to;
        }
        if (tx == 0)
            out[rowbase + ty * 4 + j] = tg[j] - (m[j] + logf(s[j]));
    }
}

// ================= launch =================
extern "C" void kernel_launch(void* const* d_in, const int* in_sizes, int n_in,
                              void* d_out, int out_size) {
    const float* latent = (const float*)d_in[0];
    const float* vw     = (const float*)d_in[1];
    const float* vb     = (const float*)d_in[2];
    const int*   zi     = (const int*)d_in[3];
    const int*   y      = (const int*)d_in[4];
    float* out = (float*)d_out;

    kA1<<<B, 256>>>(latent, zi);
    kA2<<<B, 64>>>(latent, zi);
    kB <<<B, 256>>>(latent, zi);

    cudaFuncSetAttribute(kC, cudaFuncAttributeMaxDynamicSharedMemorySize, SMEM_C);
    kC<<<ROWS / 32, 256, SMEM_C>>>(vw, vb, y, out);
}

// round 5
// speedup vs baseline: 5.1441x; 5.1441x over previous
#include <cuda_runtime.h>
#include <cuda_fp16.h>
#include <math_constants.h>
#include <cstdint>

// ---------------- problem constants ----------------
#define B_     32
#define S_     64
#define E_     128
#define TSTEP  256
#define VOCAB  32000
#define ROWS   8192
#define CPS    125            // chunks (of 128 vocab) per slice; 2 slices
#define L2E    1.4426950408889634f

// ---------------- scratch ----------------
__device__ float g_scores[B_*S_*S_];
__device__ float g_xtran [B_*S_*S_];
__device__ float g_att0  [B_*S_];
__device__ float g_A     [B_*TSTEP*S_];
__device__ float g_zs    [ROWS*E_];
__device__ __align__(16) unsigned short g_w16[VOCAB*E_];
__device__ __align__(16) unsigned short g_z16[ROWS*E_];
__device__ float g_eps[8*ROWS];
__device__ float g_tg [ROWS];

// ---------------- helpers ----------------
__device__ __forceinline__ uint32_t smem_u32(const void* p) {
    uint32_t a;
    asm("{ .reg .u64 t; cvta.to.shared.u64 t, %1; cvt.u32.u64 %0, t; }" : "=r"(a) : "l"(p));
    return a;
}
__device__ __forceinline__ void cpa16(uint32_t dst, const void* src) {
    asm volatile("cp.async.cg.shared.global [%0], [%1], 16;" :: "r"(dst), "l"(src));
}
#define CP_COMMIT() asm volatile("cp.async.commit_group;" ::: "memory")
#define CP_WAIT1()  asm volatile("cp.async.wait_group 1;" ::: "memory")

__device__ __forceinline__ void ldm_x4(uint32_t addr, uint32_t& r0, uint32_t& r1, uint32_t& r2, uint32_t& r3) {
    asm volatile("ldmatrix.sync.aligned.m8n8.x4.shared.b16 {%0,%1,%2,%3}, [%4];"
        : "=r"(r0), "=r"(r1), "=r"(r2), "=r"(r3) : "r"(addr));
}
__device__ __forceinline__ void ldm_x2(uint32_t addr, uint32_t& r0, uint32_t& r1) {
    asm volatile("ldmatrix.sync.aligned.m8n8.x2.shared.b16 {%0,%1}, [%2];"
        : "=r"(r0), "=r"(r1) : "r"(addr));
}
__device__ __forceinline__ void mma16816(float* d, const uint32_t* a, const uint32_t* b) {
    asm volatile("mma.sync.aligned.m16n8k16.row.col.f32.f16.f16.f32 "
        "{%0,%1,%2,%3}, {%4,%5,%6,%7}, {%8,%9}, {%0,%1,%2,%3};"
        : "+f"(d[0]), "+f"(d[1]), "+f"(d[2]), "+f"(d[3])
        : "r"(a[0]), "r"(a[1]), "r"(a[2]), "r"(a[3]), "r"(b[0]), "r"(b[1]));
}
// exp(l-30) = 2^y, y=(acc)*L2E + bl2;  bl2 = (bias-30)*L2E (pre-staged).
// Magic-round range reduction + deg-4 Taylor of 2^f + exponent splice. No MUFU.
__device__ __forceinline__ void expacc(float acc, float bl2, float& rs) {
    float y = fmaf(acc, L2E, bl2);
    float t = __fadd_rn(y, 12582912.0f);
    float n = __fadd_rn(t, -12582912.0f);
    float f = __fadd_rn(y, -n);
    float p = fmaf(0.009618129107f, f, 0.055504108664f);
    p = fmaf(p, f, 0.240226506959f);
    p = fmaf(p, f, 0.693147180560f);
    p = fmaf(p, f, 1.0f);
    uint32_t sb2 = (__float_as_uint(t) + 127u) << 23;
    rs = fmaf(p, __uint_as_float(sb2), rs);
}

// ================= Kernel A1: scores =================
__global__ void kA1(const float* __restrict__ latent, const int* __restrict__ zi) {
    __shared__ float xkS[64 * 129];
    int b = blockIdx.x, tid = threadIdx.x;
    const float* xq = latent + (size_t)zi[(b >> 2)]     * 32768 + (size_t)(b & 3) * 8192;
    const float* xk = latent + (size_t)zi[8 + (b >> 2)] * 32768 + (size_t)(b & 3) * 8192;
    for (int idx = tid; idx < 8192; idx += 256)
        xkS[(idx >> 7) * 129 + (idx & 127)] = __ldg(xk + idx);
    __syncthreads();
    int t = tid & 63, sg = tid >> 6;
    for (int i = 0; i < 16; i++) {
        int s = sg + 4 * i;
        float acc = 0.f;
        const float4* qp = (const float4*)(xq + s * 128);
        #pragma unroll 8
        for (int e4 = 0; e4 < 32; e4++) {
            float4 q = __ldg(qp + e4);
            const float* kp = &xkS[t * 129 + e4 * 4];
            acc += q.x * kp[0] + q.y * kp[1] + q.z * kp[2] + q.w * kp[3];
        }
        g_scores[b * 4096 + s * 64 + t] = acc * 0.08838834764831843f;
    }
}

// ================= Kernel A2: column softmax + att0 =================
__global__ void kA2(const float* __restrict__ latent, const int* __restrict__ zi) {
    int b = blockIdx.x, t = threadIdx.x;
    const float* col = g_scores + b * 4096 + t;
    float mx = -CUDART_INF_F;
    for (int s = 0; s < 64; s++) mx = fmaxf(mx, col[s * 64]);
    float sum = 0.f;
    for (int s = 0; s < 64; s++) {
        float e = __expf(col[s * 64] - mx);
        g_xtran[b * 4096 + s * 64 + t] = e;
        sum += e;
    }
    float inv = 1.f / sum;
    for (int s = 0; s < 64; s++) g_xtran[b * 4096 + s * 64 + t] *= inv;

    const float* ip = latent + (size_t)zi[24 + (b >> 2)] * 32768 + (size_t)(b & 3) * 8192;
    float xi = __ldg(ip + t * 128);
    __shared__ float smv[64];
    smv[t] = xi; __syncthreads();
    float m2 = -CUDART_INF_F;
    for (int s = 0; s < 64; s++) m2 = fmaxf(m2, smv[s]);
    float e2 = __expf(xi - m2);
    __syncthreads(); smv[t] = e2; __syncthreads();
    float su = 0.f;
    for (int s = 0; s < 64; s++) su += smv[s];
    g_att0[b * 64 + t] = e2 / su;
}

// ================= Kernel B: recurrence + zs =================
__global__ __launch_bounds__(256) void kB(const float* __restrict__ latent, const int* __restrict__ zi) {
    __shared__ float xvS[64 * 128];
    __shared__ float attS[2][64];
    __shared__ float red[256];
    __shared__ float As[32 * 64];
    int b = blockIdx.x, tid = threadIdx.x;
    const float* xv = latent + (size_t)zi[16 + (b >> 2)] * 32768 + (size_t)(b & 3) * 8192;
    for (int idx = tid; idx < 8192; idx += 256) xvS[idx] = __ldg(xv + idx);

    int tp = tid & 63, c = tid >> 6;
    float xtc[16];
    #pragma unroll
    for (int i = 0; i < 16; i++) xtc[i] = g_xtran[b * 4096 + (c * 16 + i) * 64 + tp];
    if (tid < 64) attS[0][tid] = g_att0[b * 64 + tid];
    __syncthreads();

    int p = 0;
    for (int t = 0; t < 256; t++) {
        float partial = 0.f;
        #pragma unroll
        for (int i = 0; i < 16; i++) partial += attS[p][c * 16 + i] * xtc[i];
        red[tid] = partial;
        __syncthreads();
        if (c == 0) {
            g_A[(b * 256 + t) * 64 + tp] = attS[p][tp];
            attS[p ^ 1][tp] = red[tp] + red[64 + tp] + red[128 + tp] + red[192 + tp];
        }
        __syncthreads();
        p ^= 1;
    }

    int e = tid & 127, h = tid >> 7;
    for (int tb = 0; tb < 8; tb++) {
        __syncthreads();
        for (int k = tid; k < 2048; k += 256) As[k] = g_A[(b * 256 + tb * 32) * 64 + k];
        __syncthreads();
        for (int i = 0; i < 16; i++) {
            int tl = h * 16 + i;
            float acc = 0.f;
            #pragma unroll
            for (int s2 = 0; s2 < 64; s2++) acc += As[tl * 64 + s2] * xvS[s2 * 128 + e];
            g_zs[((size_t)b * 256 + tb * 32 + tl) * 128 + e] = acc;
        }
    }
}

// ================= conversion kernels: f32 -> fp16 =================
__device__ __forceinline__ void cvt8(const float* src, unsigned short* dst) {
    float4 a = *(const float4*)src;
    float4 b = *(const float4*)(src + 4);
    __half2 h0 = __floats2half2_rn(a.x, a.y);
    __half2 h1 = __floats2half2_rn(a.z, a.w);
    __half2 h2 = __floats2half2_rn(b.x, b.y);
    __half2 h3 = __floats2half2_rn(b.z, b.w);
    uint4 o;
    o.x = *(uint32_t*)&h0; o.y = *(uint32_t*)&h1;
    o.z = *(uint32_t*)&h2; o.w = *(uint32_t*)&h3;
    *(uint4*)dst = o;
}
__global__ __launch_bounds__(256) void kWc(const float* __restrict__ vw) {
    size_t i = ((size_t)blockIdx.x * 256 + threadIdx.x) * 8;
    cvt8(vw + i, g_w16 + i);
}
__global__ __launch_bounds__(256) void kZc() {
    size_t i = ((size_t)blockIdx.x * 256 + threadIdx.x) * 8;
    cvt8(g_zs + i, g_z16 + i);
}

// ================= Kernel T: exact fp32 target logits =================
__global__ __launch_bounds__(256) void kT(const float* __restrict__ vw,
                                          const float* __restrict__ vb,
                                          const int*   __restrict__ y) {
    int r = blockIdx.x * 8 + (threadIdx.x >> 5);
    int lane = threadIdx.x & 31;
    int t = __ldg(y + r);
    float4 z = *(const float4*)(g_zs + (size_t)r * 128 + lane * 4);
    float4 w = *(const float4*)(vw + (size_t)t * 128 + lane * 4);
    float d = z.x * w.x + z.y * w.y + z.z * w.z + z.w * w.w;
    #pragma unroll
    for (int off = 16; off; off >>= 1) d += __shfl_xor_sync(0xffffffffu, d, off);
    if (lane == 0) g_tg[r] = d + __ldg(vb + t);
}

// ================= Kernel C3: HMMA GEMM + fused poly-exp logsumexp =================
#define PITCH   272                 // bytes per smem row (128 fp16 + 16B pad)
#define SM_A    0
#define SM_B0   34816
#define SM_BL2  104448              // 2 x 128 floats
#define SMEM_KC 105472

__global__ __launch_bounds__(256, 1) void kC3(const float* __restrict__ vb) {
    extern __shared__ char sm[];
    uint32_t sb = smem_u32(sm);
    int tid = threadIdx.x, lane = tid & 31, wid = tid >> 5;
    int warp_m = wid >> 2, warp_n = wid & 3;
    int mtile = blockIdx.x & 63, slice = blockIdx.x >> 6;
    int chunk0 = slice * CPS;

    const char* gz = (const char*)g_z16;
    const char* gw = (const char*)g_w16;
    float* bl2 = (float*)(sm + SM_BL2);

    // prologue: A tile + B chunk0 (group0), B chunk1 (group1)
    #pragma unroll
    for (int i = 0; i < 8; i++) {
        int idx = tid + i * 256, row = idx >> 4, part = idx & 15;
        cpa16(sb + SM_A + row * PITCH + part * 16, gz + ((size_t)mtile << 15) + ((size_t)idx << 4));
    }
    #pragma unroll
    for (int i = 0; i < 8; i++) {
        int idx = tid + i * 256, row = idx >> 4, part = idx & 15;
        cpa16(sb + SM_B0 + row * PITCH + part * 16, gw + ((size_t)chunk0 << 15) + ((size_t)idx << 4));
    }
    CP_COMMIT();
    #pragma unroll
    for (int i = 0; i < 8; i++) {
        int idx = tid + i * 256, row = idx >> 4, part = idx & 15;
        cpa16(sb + SM_B0 + 34816 + row * PITCH + part * 16,
              gw + ((size_t)(chunk0 + 1) << 15) + ((size_t)idx << 4));
    }
    CP_COMMIT();
    if (tid < 128) bl2[tid] = fmaf(__ldg(vb + chunk0 * 128 + tid), L2E, -30.f * L2E);

    // per-thread ldmatrix bases
    uint32_t aBase = sb + SM_A + (uint32_t)(warp_m * 64 + (lane & 15)) * PITCH + (uint32_t)(lane >> 4) * 16;
    uint32_t bRowOff = (uint32_t)(warp_n * 32 + (lane & 7)) * PITCH + (uint32_t)((lane >> 3) & 1) * 16;

    float rs[8];
    #pragma unroll
    for (int k = 0; k < 8; k++) rs[k] = 0.f;

    for (int c = 0; c < CPS; c++) {
        int p = c & 1;
        CP_WAIT1();
        __syncthreads();
        uint32_t Bbase = sb + SM_B0 + (uint32_t)p * 34816 + bRowOff;

        float d[4][4][4];
        #pragma unroll
        for (int mt = 0; mt < 4; mt++)
            #pragma unroll
            for (int nt = 0; nt < 4; nt++)
                #pragma unroll
                for (int q = 0; q < 4; q++) d[mt][nt][q] = 0.f;

        #pragma unroll
        for (int ks = 0; ks < 8; ks++) {
            uint32_t a[4][4], b[4][2];
            #pragma unroll
            for (int mt = 0; mt < 4; mt++)
                ldm_x4(aBase + (uint32_t)(mt * 16) * PITCH + (uint32_t)(ks * 32),
                       a[mt][0], a[mt][1], a[mt][2], a[mt][3]);
            #pragma unroll
            for (int nt = 0; nt < 4; nt++)
                ldm_x2(Bbase + (uint32_t)(nt * 8) * PITCH + (uint32_t)(ks * 32),
                       b[nt][0], b[nt][1]);
            #pragma unroll
            for (int mt = 0; mt < 4; mt++)
                #pragma unroll
                for (int nt = 0; nt < 4; nt++)
                    mma16816(d[mt][nt], a[mt], b[nt]);
        }

        // stage next chunk's bias-terms
        if (tid < 128 && c + 1 < CPS)
            bl2[((c + 1) & 1) * 128 + tid] =
                fmaf(__ldg(vb + (chunk0 + c + 1) * 128 + tid), L2E, -30.f * L2E);

        // epilogue: poly-exp accumulate into row sums
        const float* bl2c = bl2 + (c & 1) * 128;
        #pragma unroll
        for (int mt = 0; mt < 4; mt++) {
            #pragma unroll
            for (int nt = 0; nt < 4; nt++) {
                int col0 = warp_n * 32 + nt * 8 + (lane & 3) * 2;
                float2 bv = *(const float2*)&bl2c[col0];
                expacc(d[mt][nt][0], bv.x, rs[mt * 2 + 0]);
                expacc(d[mt][nt][1], bv.y, rs[mt * 2 + 0]);
                expacc(d[mt][nt][2], bv.x, rs[mt * 2 + 1]);
                expacc(d[mt][nt][3], bv.y, rs[mt * 2 + 1]);
            }
        }
        __syncthreads();
        // prefetch chunk c+2 into buffer p
        if (c + 2 < CPS) {
            #pragma unroll
            for (int i = 0; i < 8; i++) {
                int idx = tid + i * 256, row = idx >> 4, part = idx & 15;
                cpa16(sb + SM_B0 + (uint32_t)p * 34816 + row * PITCH + part * 16,
                      gw + ((size_t)(chunk0 + c + 2) << 15) + ((size_t)idx << 4));
            }
        }
        CP_COMMIT();
    }

    // reduce across the 4 lanes sharing each row; write per-(slice, warp_n) partials
    #pragma unroll
    for (int k = 0; k < 8; k++) {
        float s = rs[k];
        s += __shfl_xor_sync(0xffffffffu, s, 1);
        s += __shfl_xor_sync(0xffffffffu, s, 2);
        if ((lane & 3) == 0) {
            int mt = k >> 1, rp = k & 1;
            int row = mtile * 128 + warp_m * 64 + mt * 16 + (lane >> 2) + rp * 8;
            g_eps[(slice * 4 + warp_n) * ROWS + row] = s;
        }
    }
}

// ================= Kernel F: merge =================
__global__ void kF(float* __restrict__ out) {
    int r = blockIdx.x * 256 + threadIdx.x;
    float se = 0.f;
    #pragma unroll
    for (int s = 0; s < 8; s++) se += g_eps[s * ROWS + r];
    out[r] = g_tg[r] - 30.f - logf(se);
}

// ================= launch =================
extern "C" void kernel_launch(void* const* d_in, const int* in_sizes, int n_in,
                              void* d_out, int out_size) {
    const float* latent = (const float*)d_in[0];
    const float* vw     = (const float*)d_in[1];
    const float* vb     = (const float*)d_in[2];
    const int*   zi     = (const int*)d_in[3];
    const int*   y      = (const int*)d_in[4];
    float* out = (float*)d_out;

    kWc<<<2000, 256>>>(vw);
    kA1<<<B_, 256>>>(latent, zi);
    kA2<<<B_, 64>>>(latent, zi);
    kB <<<B_, 256>>>(latent, zi);
    kZc<<<512, 256>>>();
    kT <<<1024, 256>>>(vw, vb, y);

    cudaFuncSetAttribute(kC3, cudaFuncAttributeMaxDynamicSharedMemorySize, SMEM_KC);
    kC3<<<128, 256, SMEM_KC>>>(vb);
    kF<<<32, 256>>>(out);
}

// round 6
// speedup vs baseline: 5.3123x; 1.0327x over previous
#include <cuda_runtime.h>
#include <cuda_fp16.h>
#include <math_constants.h>
#include <cstdint>

// ---------------- problem constants ----------------
#define B_     32
#define S_     64
#define E_     128
#define TSTEP  256
#define VOCAB  32000
#define ROWS   8192
#define CPS    125            // chunks (of 128 vocab) per slice; 2 slices
#define L2E    1.4426950408889634f

// ---------------- scratch ----------------
__device__ float g_scores[B_*S_*S_];
__device__ float g_xtran [B_*S_*S_];
__device__ float g_att0  [B_*S_];
__device__ float g_A     [B_*TSTEP*S_];
__device__ float g_zs    [ROWS*E_];
__device__ __align__(16) unsigned short g_w16[VOCAB*E_];
__device__ __align__(16) unsigned short g_z16[ROWS*E_];
__device__ float g_eps[8*ROWS];
__device__ float g_tg [ROWS];

// ---------------- helpers ----------------
__device__ __forceinline__ uint32_t smem_u32(const void* p) {
    uint32_t a;
    asm("{ .reg .u64 t; cvta.to.shared.u64 t, %1; cvt.u32.u64 %0, t; }" : "=l"(*(unsigned long long*)&a) : "l"(p));
    return a;
}
__device__ __forceinline__ uint32_t smem_u32b(const void* p) {
    uint32_t a;
    asm("{ .reg .u64 t; cvta.to.shared.u64 t, %1; cvt.u32.u64 %0, t; }" : "=r"(a) : "l"(p));
    return a;
}
__device__ __forceinline__ void cpa16(uint32_t dst, const void* src) {
    asm volatile("cp.async.cg.shared.global [%0], [%1], 16;" :: "r"(dst), "l"(src));
}
#define CP_COMMIT() asm volatile("cp.async.commit_group;" ::: "memory")
#define CP_WAIT1()  asm volatile("cp.async.wait_group 1;" ::: "memory")

__device__ __forceinline__ void ldm_x4(uint32_t addr, uint32_t& r0, uint32_t& r1, uint32_t& r2, uint32_t& r3) {
    asm volatile("ldmatrix.sync.aligned.m8n8.x4.shared.b16 {%0,%1,%2,%3}, [%4];"
        : "=r"(r0), "=r"(r1), "=r"(r2), "=r"(r3) : "r"(addr));
}
__device__ __forceinline__ void ldm_x2(uint32_t addr, uint32_t& r0, uint32_t& r1) {
    asm volatile("ldmatrix.sync.aligned.m8n8.x2.shared.b16 {%0,%1}, [%2];"
        : "=r"(r0), "=r"(r1) : "r"(addr));
}
__device__ __forceinline__ void mma16816(float* d, const uint32_t* a, const uint32_t* b) {
    asm volatile("mma.sync.aligned.m16n8k16.row.col.f32.f16.f16.f32 "
        "{%0,%1,%2,%3}, {%4,%5,%6,%7}, {%8,%9}, {%0,%1,%2,%3};"
        : "+f"(d[0]), "+f"(d[1]), "+f"(d[2]), "+f"(d[3])
        : "r"(a[0]), "r"(a[1]), "r"(a[2]), "r"(a[3]), "r"(b[0]), "r"(b[1]));
}

typedef unsigned long long u64t;
__device__ __forceinline__ u64t pk2(float lo, float hi) {
    u64t r; asm("mov.b64 %0, {%1, %2};" : "=l"(r) : "f"(lo), "f"(hi)); return r;
}
__device__ __forceinline__ u64t fma2v(u64t a, u64t b, u64t c) {
    u64t r; asm("fma.rn.f32x2 %0, %1, %2, %3;" : "=l"(r) : "l"(a), "l"(b), "l"(c)); return r;
}
// packed exp(l-30) accumulate. bl2 pre-biased: bias*L2E - 30*L2E + 127.
// y' = acc*L2E + bl2 ; round via magic ; 2^f poly deg4 ; exponent splice = t_bits<<23.
__device__ __forceinline__ void expacc2(u64t acc, u64t bl2, u64t L2E2, u64t MG2, u64t NEG1,
                                        u64t C4, u64t C3, u64t C2, u64t C1, u64t ONE2, u64t& rs) {
    u64t y = fma2v(acc, L2E2, bl2);
    u64t t = fma2v(y, ONE2, MG2);        // y + magic
    u64t n = fma2v(MG2, NEG1, t);        // t - magic
    u64t f = fma2v(n, NEG1, y);          // y - n
    u64t p = fma2v(C4, f, C3);
    p = fma2v(p, f, C2);
    p = fma2v(p, f, C1);
    p = fma2v(p, f, ONE2);
    uint32_t t0, t1;
    asm("mov.b64 {%0, %1}, %2;" : "=r"(t0), "=r"(t1) : "l"(t));
    t0 <<= 23; t1 <<= 23;
    u64t sc; asm("mov.b64 %0, {%1, %2};" : "=l"(sc) : "r"(t0), "r"(t1));
    rs = fma2v(p, sc, rs);
}

// ================= Kernel A1: scores =================
__global__ void kA1(const float* __restrict__ latent, const int* __restrict__ zi) {
    __shared__ float xkS[64 * 129];
    int b = blockIdx.x, tid = threadIdx.x;
    const float* xq = latent + (size_t)zi[(b >> 2)]     * 32768 + (size_t)(b & 3) * 8192;
    const float* xk = latent + (size_t)zi[8 + (b >> 2)] * 32768 + (size_t)(b & 3) * 8192;
    for (int idx = tid; idx < 8192; idx += 256)
        xkS[(idx >> 7) * 129 + (idx & 127)] = __ldg(xk + idx);
    __syncthreads();
    int t = tid & 63, sg = tid >> 6;
    for (int i = 0; i < 16; i++) {
        int s = sg + 4 * i;
        float acc = 0.f;
        const float4* qp = (const float4*)(xq + s * 128);
        #pragma unroll 8
        for (int e4 = 0; e4 < 32; e4++) {
            float4 q = __ldg(qp + e4);
            const float* kp = &xkS[t * 129 + e4 * 4];
            acc += q.x * kp[0] + q.y * kp[1] + q.z * kp[2] + q.w * kp[3];
        }
        g_scores[b * 4096 + s * 64 + t] = acc * 0.08838834764831843f;
    }
}

// ================= Kernel A2: column softmax + att0 =================
__global__ void kA2(const float* __restrict__ latent, const int* __restrict__ zi) {
    int b = blockIdx.x, t = threadIdx.x;
    const float* col = g_scores + b * 4096 + t;
    float mx = -CUDART_INF_F;
    for (int s = 0; s < 64; s++) mx = fmaxf(mx, col[s * 64]);
    float sum = 0.f;
    for (int s = 0; s < 64; s++) {
        float e = __expf(col[s * 64] - mx);
        g_xtran[b * 4096 + s * 64 + t] = e;
        sum += e;
    }
    float inv = 1.f / sum;
    for (int s = 0; s < 64; s++) g_xtran[b * 4096 + s * 64 + t] *= inv;

    const float* ip = latent + (size_t)zi[24 + (b >> 2)] * 32768 + (size_t)(b & 3) * 8192;
    float xi = __ldg(ip + t * 128);
    __shared__ float smv[64];
    smv[t] = xi; __syncthreads();
    float m2 = -CUDART_INF_F;
    for (int s = 0; s < 64; s++) m2 = fmaxf(m2, smv[s]);
    float e2 = __expf(xi - m2);
    __syncthreads(); smv[t] = e2; __syncthreads();
    float su = 0.f;
    for (int s = 0; s < 64; s++) su += smv[s];
    g_att0[b * 64 + t] = e2 / su;
}

// ================= Kernel B1: log-doubling Markov scan =================
// A[t] = att0 * M^t, built by doubling: A[k:2k] = A[0:k] * M^k; M^{2k} = (M^k)^2.
#define KB1_SMEM ((4352*2 + 16384) * 4)
__global__ __launch_bounds__(512) void kB1() {
    extern __shared__ float s[];
    float* M0 = s;
    float* M1 = s + 4352;          // pitch 68 floats
    float* A  = s + 8704;          // 256 x 64
    int b = blockIdx.x, tid = threadIdx.x;

    for (int i = tid; i < 4096; i += 512)
        M0[(i >> 6) * 68 + (i & 63)] = g_xtran[b * 4096 + i];
    if (tid < 64) A[tid] = g_att0[b * 64 + tid];
    __syncthreads();

    float* Mp = M0; float* Mq = M1;
    int cur = 1;
    #pragma unroll 1
    for (int it = 0; it < 8; it++) {
        int groups = cur * 16;                     // 4 cols per group
        for (int o = tid; o < groups; o += 512) {
            int row = o >> 4, c4 = (o & 15) * 4;
            float ax = 0.f, ay = 0.f, az = 0.f, aw = 0.f;
            const float* ar = A + row * 64;
            #pragma unroll 8
            for (int ss = 0; ss < 64; ss++) {
                float a = ar[ss];
                float4 m = *(const float4*)&Mp[ss * 68 + c4];
                ax += a * m.x; ay += a * m.y; az += a * m.z; aw += a * m.w;
            }
            float4 o4 = {ax, ay, az, aw};
            *(float4*)&A[(cur + row) * 64 + c4] = o4;
        }
        if (it < 7) {
            for (int o = tid; o < 1024; o += 512) {
                int rr = o >> 4, c4 = (o & 15) * 4;
                float ax = 0.f, ay = 0.f, az = 0.f, aw = 0.f;
                const float* mr = Mp + rr * 68;
                #pragma unroll 8
                for (int ss = 0; ss < 64; ss++) {
                    float a = mr[ss];
                    float4 m = *(const float4*)&Mp[ss * 68 + c4];
                    ax += a * m.x; ay += a * m.y; az += a * m.z; aw += a * m.w;
                }
                Mq[rr * 68 + c4]     = ax;
                Mq[rr * 68 + c4 + 1] = ay;
                Mq[rr * 68 + c4 + 2] = az;
                Mq[rr * 68 + c4 + 3] = aw;
            }
            float* tmp = Mp; Mp = Mq; Mq = tmp;
        }
        __syncthreads();
        cur <<= 1;
    }
    for (int i = tid; i < 4096; i += 512)
        *(float4*)&g_A[(size_t)b * 16384 + i * 4] = *(const float4*)&A[i * 4];
}

// ================= Kernel B2: zs = A * xv, + fp16 convert (wide) =================
__global__ __launch_bounds__(256) void kB2(const float* __restrict__ latent, const int* __restrict__ zi) {
    __shared__ float As[2048];
    __shared__ float xvS[8192];
    int b = blockIdx.x >> 3, tb = blockIdx.x & 7;
    int tid = threadIdx.x;
    const float* xv = latent + (size_t)zi[16 + (b >> 2)] * 32768 + (size_t)(b & 3) * 8192;
    for (int i = tid; i < 8192; i += 256) xvS[i] = __ldg(xv + i);
    for (int i = tid; i < 2048; i += 256) As[i] = g_A[(size_t)(b * 256 + tb * 32) * 64 + i];
    __syncthreads();
    int e = tid & 127, h = tid >> 7;
    for (int i = 0; i < 16; i++) {
        int tl = h * 16 + i;
        float acc = 0.f;
        #pragma unroll
        for (int s2 = 0; s2 < 64; s2++) acc += As[tl * 64 + s2] * xvS[s2 * 128 + e];
        size_t row = (size_t)b * 256 + tb * 32 + tl;
        g_zs[row * 128 + e] = acc;
        g_z16[row * 128 + e] = __half_as_ushort(__float2half(acc));
    }
}

// ================= Kernel Wc: vocab_w f32 -> fp16 =================
__global__ __launch_bounds__(256) void kWc(const float* __restrict__ vw) {
    size_t i = ((size_t)blockIdx.x * 256 + threadIdx.x) * 8;
    float4 a = *(const float4*)(vw + i);
    float4 b = *(const float4*)(vw + i + 4);
    __half2 h0 = __floats2half2_rn(a.x, a.y);
    __half2 h1 = __floats2half2_rn(a.z, a.w);
    __half2 h2 = __floats2half2_rn(b.x, b.y);
    __half2 h3 = __floats2half2_rn(b.z, b.w);
    uint4 o;
    o.x = *(uint32_t*)&h0; o.y = *(uint32_t*)&h1;
    o.z = *(uint32_t*)&h2; o.w = *(uint32_t*)&h3;
    *(uint4*)(g_w16 + i) = o;
}

// ================= Kernel T: exact fp32 target logits =================
__global__ __launch_bounds__(256) void kT(const float* __restrict__ vw,
                                          const float* __restrict__ vb,
                                          const int*   __restrict__ y) {
    int r = blockIdx.x * 8 + (threadIdx.x >> 5);
    int lane = threadIdx.x & 31;
    int t = __ldg(y + r);
    float4 z = *(const float4*)(g_zs + (size_t)r * 128 + lane * 4);
    float4 w = *(const float4*)(vw + (size_t)t * 128 + lane * 4);
    float d = z.x * w.x + z.y * w.y + z.z * w.z + z.w * w.w;
    #pragma unroll
    for (int off = 16; off; off >>= 1) d += __shfl_xor_sync(0xffffffffu, d, off);
    if (lane == 0) g_tg[r] = d + __ldg(vb + t);
}

// ================= Kernel C3: HMMA GEMM + packed poly-exp logsumexp =================
#define PITCH   272
#define SM_A    0
#define SM_B0   34816
#define SM_BL2  104448
#define SMEM_KC 105472

__global__ __launch_bounds__(256, 1) void kC3(const float* __restrict__ vb) {
    extern __shared__ char sm[];
    uint32_t sb = smem_u32b(sm);
    int tid = threadIdx.x, lane = tid & 31, wid = tid >> 5;
    int warp_m = wid >> 2, warp_n = wid & 3;
    int mtile = blockIdx.x & 63, slice = blockIdx.x >> 6;
    int chunk0 = slice * CPS;

    const char* gz = (const char*)g_z16;
    const char* gw = (const char*)g_w16;
    float* bl2 = (float*)(sm + SM_BL2);

    // packed constants
    const u64t L2E2 = pk2(L2E, L2E);
    const u64t MG2  = pk2(12582912.0f, 12582912.0f);
    const u64t NEG1 = pk2(-1.0f, -1.0f);
    const u64t C4   = pk2(0.009618129107f, 0.009618129107f);
    const u64t C3   = pk2(0.055504108664f, 0.055504108664f);
    const u64t C2   = pk2(0.240226506959f, 0.240226506959f);
    const u64t C1   = pk2(0.693147180560f, 0.693147180560f);
    const u64t ONE2 = pk2(1.0f, 1.0f);
    const float BIAS = 127.0f - 30.f * L2E;

    // prologue: A tile + B chunk0 (group0), B chunk1 (group1)
    #pragma unroll
    for (int i = 0; i < 8; i++) {
        int idx = tid + i * 256, row = idx >> 4, part = idx & 15;
        cpa16(sb + SM_A + row * PITCH + part * 16, gz + ((size_t)mtile << 15) + ((size_t)idx << 4));
    }
    #pragma unroll
    for (int i = 0; i < 8; i++) {
        int idx = tid + i * 256, row = idx >> 4, part = idx & 15;
        cpa16(sb + SM_B0 + row * PITCH + part * 16, gw + ((size_t)chunk0 << 15) + ((size_t)idx << 4));
    }
    CP_COMMIT();
    #pragma unroll
    for (int i = 0; i < 8; i++) {
        int idx = tid + i * 256, row = idx >> 4, part = idx & 15;
        cpa16(sb + SM_B0 + 34816 + row * PITCH + part * 16,
              gw + ((size_t)(chunk0 + 1) << 15) + ((size_t)idx << 4));
    }
    CP_COMMIT();
    if (tid < 128) bl2[tid] = fmaf(__ldg(vb + chunk0 * 128 + tid), L2E, BIAS);

    uint32_t aBase = sb + SM_A + (uint32_t)(warp_m * 64 + (lane & 15)) * PITCH + (uint32_t)(lane >> 4) * 16;
    uint32_t bRowOff = (uint32_t)(warp_n * 32 + (lane & 7)) * PITCH + (uint32_t)((lane >> 3) & 1) * 16;

    u64t RS[8];
    #pragma unroll
    for (int k = 0; k < 8; k++) RS[k] = 0ULL;

    for (int c = 0; c < CPS; c++) {
        int p = c & 1;
        CP_WAIT1();
        __syncthreads();
        uint32_t Bbase = sb + SM_B0 + (uint32_t)p * 34816 + bRowOff;

        float d[4][4][4];
        #pragma unroll
        for (int mt = 0; mt < 4; mt++)
            #pragma unroll
            for (int nt = 0; nt < 4; nt++)
                #pragma unroll
                for (int q = 0; q < 4; q++) d[mt][nt][q] = 0.f;

        #pragma unroll
        for (int ks = 0; ks < 8; ks++) {
            uint32_t a[4][4], b[4][2];
            #pragma unroll
            for (int mt = 0; mt < 4; mt++)
                ldm_x4(aBase + (uint32_t)(mt * 16) * PITCH + (uint32_t)(ks * 32),
                       a[mt][0], a[mt][1], a[mt][2], a[mt][3]);
            #pragma unroll
            for (int nt = 0; nt < 4; nt++)
                ldm_x2(Bbase + (uint32_t)(nt * 8) * PITCH + (uint32_t)(ks * 32),
                       b[nt][0], b[nt][1]);
            #pragma unroll
            for (int mt = 0; mt < 4; mt++)
                #pragma unroll
                for (int nt = 0; nt < 4; nt++)
                    mma16816(d[mt][nt], a[mt], b[nt]);
        }

        if (tid < 128 && c + 1 < CPS)
            bl2[((c + 1) & 1) * 128 + tid] =
                fmaf(__ldg(vb + (chunk0 + c + 1) * 128 + tid), L2E, BIAS);

        // packed epilogue
        const float* bl2c = bl2 + (c & 1) * 128;
        #pragma unroll
        for (int mt = 0; mt < 4; mt++) {
            #pragma unroll
            for (int nt = 0; nt < 4; nt++) {
                int col0 = warp_n * 32 + nt * 8 + (lane & 3) * 2;
                u64t bv = *(const u64t*)&bl2c[col0];
                u64t P01 = pk2(d[mt][nt][0], d[mt][nt][1]);
                u64t P23 = pk2(d[mt][nt][2], d[mt][nt][3]);
                expacc2(P01, bv, L2E2, MG2, NEG1, C4, C3, C2, C1, ONE2, RS[mt * 2 + 0]);
                expacc2(P23, bv, L2E2, MG2, NEG1, C4, C3, C2, C1, ONE2, RS[mt * 2 + 1]);
            }
        }
        __syncthreads();
        if (c + 2 < CPS) {
            #pragma unroll
            for (int i = 0; i < 8; i++) {
                int idx = tid + i * 256, row = idx >> 4, part = idx & 15;
                cpa16(sb + SM_B0 + (uint32_t)p * 34816 + row * PITCH + part * 16,
                      gw + ((size_t)(chunk0 + c + 2) << 15) + ((size_t)idx << 4));
            }
        }
        CP_COMMIT();
    }

    // combine packed halves, reduce over 4 lanes sharing each row, store partials
    #pragma unroll
    for (int k = 0; k < 8; k++) {
        float lo, hi;
        asm("mov.b64 {%0, %1}, %2;" : "=f"(lo), "=f"(hi) : "l"(RS[k]));
        float s = lo + hi;
        s += __shfl_xor_sync(0xffffffffu, s, 1);
        s += __shfl_xor_sync(0xffffffffu, s, 2);
        if ((lane & 3) == 0) {
            int mt = k >> 1, rp = k & 1;
            int row = mtile * 128 + warp_m * 64 + mt * 16 + (lane >> 2) + rp * 8;
            g_eps[(slice * 4 + warp_n) * ROWS + row] = s;
        }
    }
}

// ================= Kernel F: merge =================
__global__ void kF(float* __restrict__ out) {
    int r = blockIdx.x * 256 + threadIdx.x;
    float se = 0.f;
    #pragma unroll
    for (int s = 0; s < 8; s++) se += g_eps[s * ROWS + r];
    out[r] = g_tg[r] - 30.f - logf(se);
}

// ================= launch =================
extern "C" void kernel_launch(void* const* d_in, const int* in_sizes, int n_in,
                              void* d_out, int out_size) {
    const float* latent = (const float*)d_in[0];
    const float* vw     = (const float*)d_in[1];
    const float* vb     = (const float*)d_in[2];
    const int*   zi     = (const int*)d_in[3];
    const int*   y      = (const int*)d_in[4];
    float* out = (float*)d_out;

    kWc<<<2000, 256>>>(vw);
    kA1<<<B_, 256>>>(latent, zi);
    kA2<<<B_, 64>>>(latent, zi);

    cudaFuncSetAttribute(kB1, cudaFuncAttributeMaxDynamicSharedMemorySize, KB1_SMEM);
    kB1<<<B_, 512, KB1_SMEM>>>();
    kB2<<<256, 256>>>(latent, zi);
    kT <<<1024, 256>>>(vw, vb, y);

    cudaFuncSetAttribute(kC3, cudaFuncAttributeMaxDynamicSharedMemorySize, SMEM_KC);
    kC3<<<128, 256, SMEM_KC>>>(vb);
    kF<<<32, 256>>>(out);
}

// round 7
// speedup vs baseline: 5.5122x; 1.0376x over previous
#include <cuda_runtime.h>
#include <cuda_fp16.h>
#include <math_constants.h>
#include <cstdint>

// ---------------- problem constants ----------------
#define B_     32
#define S_     64
#define E_     128
#define TSTEP  256
#define VOCAB  32000
#define ROWS   8192
#define CPS    125            // chunks (of 128 vocab) per slice; 2 slices
#define L2E    1.4426950408889634f

// ---------------- scratch ----------------
__device__ float g_scores[B_*S_*S_];
__device__ float g_xtran [B_*S_*S_];
__device__ float g_Mp    [2][B_*S_*S_];     // ping-pong M^(2^k)
__device__ float g_A     [B_*TSTEP*S_];
__device__ float g_zs    [ROWS*E_];
__device__ __align__(16) unsigned short g_w16[VOCAB*E_];
__device__ __align__(16) unsigned short g_z16[ROWS*E_];
__device__ float g_eps[8*ROWS];
__device__ float g_tg [ROWS];

// ---------------- helpers ----------------
__device__ __forceinline__ uint32_t smem_u32b(const void* p) {
    uint32_t a;
    asm("{ .reg .u64 t; cvta.to.shared.u64 t, %1; cvt.u32.u64 %0, t; }" : "=r"(a) : "l"(p));
    return a;
}
__device__ __forceinline__ void cpa16(uint32_t dst, const void* src) {
    asm volatile("cp.async.cg.shared.global [%0], [%1], 16;" :: "r"(dst), "l"(src));
}
#define CP_COMMIT() asm volatile("cp.async.commit_group;" ::: "memory")
#define CP_WAIT1()  asm volatile("cp.async.wait_group 1;" ::: "memory")

__device__ __forceinline__ void ldm_x4(uint32_t addr, uint32_t& r0, uint32_t& r1, uint32_t& r2, uint32_t& r3) {
    asm volatile("ldmatrix.sync.aligned.m8n8.x4.shared.b16 {%0,%1,%2,%3}, [%4];"
        : "=r"(r0), "=r"(r1), "=r"(r2), "=r"(r3) : "r"(addr));
}
__device__ __forceinline__ void ldm_x2(uint32_t addr, uint32_t& r0, uint32_t& r1) {
    asm volatile("ldmatrix.sync.aligned.m8n8.x2.shared.b16 {%0,%1}, [%2];"
        : "=r"(r0), "=r"(r1) : "r"(addr));
}
// fp16-accumulate HMMA (2 result regs)
__device__ __forceinline__ void mma16816h(uint32_t* d, const uint32_t* a, const uint32_t* b) {
    asm volatile("mma.sync.aligned.m16n8k16.row.col.f16.f16.f16.f16 "
        "{%0,%1}, {%2,%3,%4,%5}, {%6,%7}, {%0,%1};"
        : "+r"(d[0]), "+r"(d[1])
        : "r"(a[0]), "r"(a[1]), "r"(a[2]), "r"(a[3]), "r"(b[0]), "r"(b[1]));
}

typedef unsigned long long u64t;
__device__ __forceinline__ u64t pk2(float lo, float hi) {
    u64t r; asm("mov.b64 %0, {%1, %2};" : "=l"(r) : "f"(lo), "f"(hi)); return r;
}
__device__ __forceinline__ u64t fma2v(u64t a, u64t b, u64t c) {
    u64t r; asm("fma.rn.f32x2 %0, %1, %2, %3;" : "=l"(r) : "l"(a), "l"(b), "l"(c)); return r;
}
__device__ __forceinline__ u64t h2f2(uint32_t h) {
    __half2 hh = *(__half2*)&h;
    float2 f = __half22float2(hh);
    u64t r; asm("mov.b64 %0, {%1, %2};" : "=l"(r) : "f"(f.x), "f"(f.y));
    return r;
}
// packed exp(l-30) accumulate; bl2 = bias*L2E + (127 - 30*L2E)
__device__ __forceinline__ void expacc2(u64t acc, u64t bl2, u64t L2E2, u64t MG2, u64t NEG1,
                                        u64t C4, u64t C3, u64t C2, u64t C1, u64t ONE2, u64t& rs) {
    u64t y = fma2v(acc, L2E2, bl2);
    u64t t = fma2v(y, ONE2, MG2);        // y + magic
    u64t n = fma2v(MG2, NEG1, t);        // t - magic
    u64t f = fma2v(n, NEG1, y);          // y - n
    u64t p = fma2v(C4, f, C3);
    p = fma2v(p, f, C2);
    p = fma2v(p, f, C1);
    p = fma2v(p, f, ONE2);
    uint32_t t0, t1;
    asm("mov.b64 {%0, %1}, %2;" : "=r"(t0), "=r"(t1) : "l"(t));
    t0 <<= 23; t1 <<= 23;
    u64t sc; asm("mov.b64 %0, {%1, %2};" : "=l"(sc) : "r"(t0), "r"(t1));
    rs = fma2v(p, sc, rs);
}

// ================= Kernel A1: scores =================
__global__ void kA1(const float* __restrict__ latent, const int* __restrict__ zi) {
    __shared__ float xkS[64 * 129];
    int b = blockIdx.x, tid = threadIdx.x;
    const float* xq = latent + (size_t)zi[(b >> 2)]     * 32768 + (size_t)(b & 3) * 8192;
    const float* xk = latent + (size_t)zi[8 + (b >> 2)] * 32768 + (size_t)(b & 3) * 8192;
    for (int idx = tid; idx < 8192; idx += 256)
        xkS[(idx >> 7) * 129 + (idx & 127)] = __ldg(xk + idx);
    __syncthreads();
    int t = tid & 63, sg = tid >> 6;
    for (int i = 0; i < 16; i++) {
        int s = sg + 4 * i;
        float acc = 0.f;
        const float4* qp = (const float4*)(xq + s * 128);
        #pragma unroll 8
        for (int e4 = 0; e4 < 32; e4++) {
            float4 q = __ldg(qp + e4);
            const float* kp = &xkS[t * 129 + e4 * 4];
            acc += q.x * kp[0] + q.y * kp[1] + q.z * kp[2] + q.w * kp[3];
        }
        g_scores[b * 4096 + s * 64 + t] = acc * 0.08838834764831843f;
    }
}

// ================= Kernel A2: column softmax + att0 (A row 0) =================
__global__ void kA2(const float* __restrict__ latent, const int* __restrict__ zi) {
    int b = blockIdx.x, t = threadIdx.x;
    const float* col = g_scores + b * 4096 + t;
    float mx = -CUDART_INF_F;
    for (int s = 0; s < 64; s++) mx = fmaxf(mx, col[s * 64]);
    float sum = 0.f;
    for (int s = 0; s < 64; s++) {
        float e = __expf(col[s * 64] - mx);
        g_xtran[b * 4096 + s * 64 + t] = e;
        sum += e;
    }
    float inv = 1.f / sum;
    for (int s = 0; s < 64; s++) g_xtran[b * 4096 + s * 64 + t] *= inv;

    const float* ip = latent + (size_t)zi[24 + (b >> 2)] * 32768 + (size_t)(b & 3) * 8192;
    float xi = __ldg(ip + t * 128);
    __shared__ float smv[64];
    smv[t] = xi; __syncthreads();
    float m2 = -CUDART_INF_F;
    for (int s = 0; s < 64; s++) m2 = fmaxf(m2, smv[s]);
    float e2 = __expf(xi - m2);
    __syncthreads(); smv[t] = e2; __syncthreads();
    float su = 0.f;
    for (int s = 0; s < 64; s++) su += smv[s];
    g_A[(size_t)b * 16384 + t] = e2 / su;      // A[0] = att0
}

// ================= Kernel BD: one doubling step (wide) =================
// grid (32 batches, 4 col-splits). A[cur:2cur] = A[0:cur]*Mp ; Mdst = Mp*Mp (cols 16q).
#define KBD_SMEM (17408 + 32768)
__global__ __launch_bounds__(256) void kBD(const float* __restrict__ Msrc,
                                           float* __restrict__ Mdst,
                                           int cur, int last) {
    extern __shared__ float s[];
    float* Ms = s;                 // 64 x 68 pitch
    float* As = s + 4352;          // up to 128 x 64
    int b = blockIdx.x, q = blockIdx.y, tid = threadIdx.x;

    for (int i = tid; i < 4096; i += 256)
        Ms[(i >> 6) * 68 + (i & 63)] = Msrc[b * 4096 + i];
    for (int i = tid; i < cur * 64; i += 256)
        As[i] = g_A[(size_t)b * 16384 + i];
    __syncthreads();

    // extension: A[cur + row][cols q*16 .. +16)
    for (int o = tid; o < cur * 4; o += 256) {
        int row = o >> 2, c4 = q * 16 + (o & 3) * 4;
        float ax = 0.f, ay = 0.f, az = 0.f, aw = 0.f;
        const float* ar = As + row * 64;
        #pragma unroll 8
        for (int ss = 0; ss < 64; ss++) {
            float a = ar[ss];
            float4 m = *(const float4*)&Ms[ss * 68 + c4];
            ax += a * m.x; ay += a * m.y; az += a * m.z; aw += a * m.w;
        }
        float4 o4 = {ax, ay, az, aw};
        *(float4*)&g_A[(size_t)b * 16384 + (size_t)(cur + row) * 64 + c4] = o4;
    }
    // squaring (skip on last)
    if (!last) {
        int row = tid >> 2, c4 = q * 16 + (tid & 3) * 4;
        float ax = 0.f, ay = 0.f, az = 0.f, aw = 0.f;
        const float* mr = Ms + row * 68;
        #pragma unroll 8
        for (int ss = 0; ss < 64; ss++) {
            float a = mr[ss];
            float4 m = *(const float4*)&Ms[ss * 68 + c4];
            ax += a * m.x; ay += a * m.y; az += a * m.z; aw += a * m.w;
        }
        float4 o4 = {ax, ay, az, aw};
        *(float4*)&Mdst[b * 4096 + row * 64 + c4] = o4;
    }
}

// ================= Kernel B2: zs = A * xv, + fp16 convert (wide) =================
__global__ __launch_bounds__(256) void kB2(const float* __restrict__ latent, const int* __restrict__ zi) {
    __shared__ float As[2048];
    __shared__ float xvS[8192];
    int b = blockIdx.x >> 3, tb = blockIdx.x & 7;
    int tid = threadIdx.x;
    const float* xv = latent + (size_t)zi[16 + (b >> 2)] * 32768 + (size_t)(b & 3) * 8192;
    for (int i = tid; i < 8192; i += 256) xvS[i] = __ldg(xv + i);
    for (int i = tid; i < 2048; i += 256) As[i] = g_A[(size_t)(b * 256 + tb * 32) * 64 + i];
    __syncthreads();
    int e = tid & 127, h = tid >> 7;
    for (int i = 0; i < 16; i++) {
        int tl = h * 16 + i;
        float acc = 0.f;
        #pragma unroll
        for (int s2 = 0; s2 < 64; s2++) acc += As[tl * 64 + s2] * xvS[s2 * 128 + e];
        size_t row = (size_t)b * 256 + tb * 32 + tl;
        g_zs[row * 128 + e] = acc;
        g_z16[row * 128 + e] = __half_as_ushort(__float2half(acc));
    }
}

// ================= Kernel Wc: vocab_w f32 -> fp16 =================
__global__ __launch_bounds__(256) void kWc(const float* __restrict__ vw) {
    size_t i = ((size_t)blockIdx.x * 256 + threadIdx.x) * 8;
    float4 a = *(const float4*)(vw + i);
    float4 b = *(const float4*)(vw + i + 4);
    __half2 h0 = __floats2half2_rn(a.x, a.y);
    __half2 h1 = __floats2half2_rn(a.z, a.w);
    __half2 h2 = __floats2half2_rn(b.x, b.y);
    __half2 h3 = __floats2half2_rn(b.z, b.w);
    uint4 o;
    o.x = *(uint32_t*)&h0; o.y = *(uint32_t*)&h1;
    o.z = *(uint32_t*)&h2; o.w = *(uint32_t*)&h3;
    *(uint4*)(g_w16 + i) = o;
}

// ================= Kernel T: exact fp32 target logits =================
__global__ __launch_bounds__(256) void kT(const float* __restrict__ vw,
                                          const float* __restrict__ vb,
                                          const int*   __restrict__ y) {
    int r = blockIdx.x * 8 + (threadIdx.x >> 5);
    int lane = threadIdx.x & 31;
    int t = __ldg(y + r);
    float4 z = *(const float4*)(g_zs + (size_t)r * 128 + lane * 4);
    float4 w = *(const float4*)(vw + (size_t)t * 128 + lane * 4);
    float d = z.x * w.x + z.y * w.y + z.z * w.z + z.w * w.w;
    #pragma unroll
    for (int off = 16; off; off >>= 1) d += __shfl_xor_sync(0xffffffffu, d, off);
    if (lane == 0) g_tg[r] = d + __ldg(vb + t);
}

// ================= Kernel C3: register-A HMMA (f16 acc) + packed poly-exp =================
#define PITCH   272
#define SM_A    0
#define SM_B0   34816
#define SM_BL2  104448
#define SMEM_KC 105472

__global__ __launch_bounds__(256, 1) void kC3(const float* __restrict__ vb) {
    extern __shared__ char sm[];
    uint32_t sb = smem_u32b(sm);
    int tid = threadIdx.x, lane = tid & 31, wid = tid >> 5;
    int warp_m = wid >> 2, warp_n = wid & 3;
    int mtile = blockIdx.x & 63, slice = blockIdx.x >> 6;
    int chunk0 = slice * CPS;

    const char* gz = (const char*)g_z16;
    const char* gw = (const char*)g_w16;
    float* bl2 = (float*)(sm + SM_BL2);

    const u64t L2E2 = pk2(L2E, L2E);
    const u64t MG2  = pk2(12582912.0f, 12582912.0f);
    const u64t NEG1 = pk2(-1.0f, -1.0f);
    const u64t C4   = pk2(0.009618129107f, 0.009618129107f);
    const u64t C3   = pk2(0.055504108664f, 0.055504108664f);
    const u64t C2   = pk2(0.240226506959f, 0.240226506959f);
    const u64t C1   = pk2(0.693147180560f, 0.693147180560f);
    const u64t ONE2 = pk2(1.0f, 1.0f);
    const float BIAS = 127.0f - 30.f * L2E;

    // prologue: A tile + B chunk0 (group0), B chunk1 (group1)
    #pragma unroll
    for (int i = 0; i < 8; i++) {
        int idx = tid + i * 256, row = idx >> 4, part = idx & 15;
        cpa16(sb + SM_A + row * PITCH + part * 16, gz + ((size_t)mtile << 15) + ((size_t)idx << 4));
    }
    #pragma unroll
    for (int i = 0; i < 8; i++) {
        int idx = tid + i * 256, row = idx >> 4, part = idx & 15;
        cpa16(sb + SM_B0 + row * PITCH + part * 16, gw + ((size_t)chunk0 << 15) + ((size_t)idx << 4));
    }
    CP_COMMIT();
    #pragma unroll
    for (int i = 0; i < 8; i++) {
        int idx = tid + i * 256, row = idx >> 4, part = idx & 15;
        cpa16(sb + SM_B0 + 34816 + row * PITCH + part * 16,
              gw + ((size_t)(chunk0 + 1) << 15) + ((size_t)idx << 4));
    }
    CP_COMMIT();
    if (tid < 128) bl2[tid] = fmaf(__ldg(vb + chunk0 * 128 + tid), L2E, BIAS);

    uint32_t aBase = sb + SM_A + (uint32_t)(warp_m * 64 + (lane & 15)) * PITCH + (uint32_t)(lane >> 4) * 16;
    uint32_t bRowOff = (uint32_t)(warp_n * 32 + (lane & 7)) * PITCH + (uint32_t)((lane >> 3) & 1) * 16;

    // wait for A (+B0); hoist ALL A fragments into registers (reused 125x)
    CP_WAIT1();
    __syncthreads();
    uint32_t afr[4][8][4];
    #pragma unroll
    for (int mt = 0; mt < 4; mt++)
        #pragma unroll
        for (int ks = 0; ks < 8; ks++)
            ldm_x4(aBase + (uint32_t)(mt * 16) * PITCH + (uint32_t)(ks * 32),
                   afr[mt][ks][0], afr[mt][ks][1], afr[mt][ks][2], afr[mt][ks][3]);

    u64t RS[8];
    #pragma unroll
    for (int k = 0; k < 8; k++) RS[k] = 0ULL;

    for (int c = 0; c < CPS; c++) {
        int p = c & 1;
        CP_WAIT1();
        __syncthreads();
        uint32_t Bbase = sb + SM_B0 + (uint32_t)p * 34816 + bRowOff;

        uint32_t hd[4][4][2];
        #pragma unroll
        for (int mt = 0; mt < 4; mt++)
            #pragma unroll
            for (int nt = 0; nt < 4; nt++) { hd[mt][nt][0] = 0u; hd[mt][nt][1] = 0u; }

        #pragma unroll
        for (int ks = 0; ks < 8; ks++) {
            uint32_t b[4][2];
            #pragma unroll
            for (int nt = 0; nt < 4; nt++)
                ldm_x2(Bbase + (uint32_t)(nt * 8) * PITCH + (uint32_t)(ks * 32),
                       b[nt][0], b[nt][1]);
            #pragma unroll
            for (int mt = 0; mt < 4; mt++)
                #pragma unroll
                for (int nt = 0; nt < 4; nt++)
                    mma16816h(hd[mt][nt], afr[mt][ks], b[nt]);
        }

        if (tid < 128 && c + 1 < CPS)
            bl2[((c + 1) & 1) * 128 + tid] =
                fmaf(__ldg(vb + (chunk0 + c + 1) * 128 + tid), L2E, BIAS);

        // packed epilogue straight from f16 accumulators
        const float* bl2c = bl2 + (c & 1) * 128;
        #pragma unroll
        for (int mt = 0; mt < 4; mt++) {
            #pragma unroll
            for (int nt = 0; nt < 4; nt++) {
                int col0 = warp_n * 32 + nt * 8 + (lane & 3) * 2;
                u64t bv = *(const u64t*)&bl2c[col0];
                u64t f01 = h2f2(hd[mt][nt][0]);
                u64t f23 = h2f2(hd[mt][nt][1]);
                expacc2(f01, bv, L2E2, MG2, NEG1, C4, C3, C2, C1, ONE2, RS[mt * 2 + 0]);
                expacc2(f23, bv, L2E2, MG2, NEG1, C4, C3, C2, C1, ONE2, RS[mt * 2 + 1]);
            }
        }
        __syncthreads();
        if (c + 2 < CPS) {
            #pragma unroll
            for (int i = 0; i < 8; i++) {
                int idx = tid + i * 256, row = idx >> 4, part = idx & 15;
                cpa16(sb + SM_B0 + (uint32_t)p * 34816 + row * PITCH + part * 16,
                      gw + ((size_t)(chunk0 + c + 2) << 15) + ((size_t)idx << 4));
            }
        }
        CP_COMMIT();
    }

    #pragma unroll
    for (int k = 0; k < 8; k++) {
        float lo, hi;
        asm("mov.b64 {%0, %1}, %2;" : "=f"(lo), "=f"(hi) : "l"(RS[k]));
        float s = lo + hi;
        s += __shfl_xor_sync(0xffffffffu, s, 1);
        s += __shfl_xor_sync(0xffffffffu, s, 2);
        if ((lane & 3) == 0) {
            int mt = k >> 1, rp = k & 1;
            int row = mtile * 128 + warp_m * 64 + mt * 16 + (lane >> 2) + rp * 8;
            g_eps[(slice * 4 + warp_n) * ROWS + row] = s;
        }
    }
}

// ================= Kernel F: merge =================
__global__ void kF(float* __restrict__ out) {
    int r = blockIdx.x * 256 + threadIdx.x;
    float se = 0.f;
    #pragma unroll
    for (int s = 0; s < 8; s++) se += g_eps[s * ROWS + r];
    out[r] = g_tg[r] - 30.f - logf(se);
}

// ================= launch =================
extern "C" void kernel_launch(void* const* d_in, const int* in_sizes, int n_in,
                              void* d_out, int out_size) {
    const float* latent = (const float*)d_in[0];
    const float* vw     = (const float*)d_in[1];
    const float* vb     = (const float*)d_in[2];
    const int*   zi     = (const int*)d_in[3];
    const int*   y      = (const int*)d_in[4];
    float* out = (float*)d_out;

    static cudaStream_t s1 = nullptr;
    static cudaEvent_t e0, eW, eZ, eT;
    static float *xt = nullptr, *mp0 = nullptr, *mp1 = nullptr;
    if (!s1) {
        cudaStreamCreateWithFlags(&s1, cudaStreamNonBlocking);
        cudaEventCreateWithFlags(&e0, cudaEventDisableTiming);
        cudaEventCreateWithFlags(&eW, cudaEventDisableTiming);
        cudaEventCreateWithFlags(&eZ, cudaEventDisableTiming);
        cudaEventCreateWithFlags(&eT, cudaEventDisableTiming);
        cudaGetSymbolAddress((void**)&xt,  g_xtran);
        cudaGetSymbolAddress((void**)&mp0, g_Mp);
        mp1 = mp0 + B_ * S_ * S_;
        cudaFuncSetAttribute(kBD, cudaFuncAttributeMaxDynamicSharedMemorySize, KBD_SMEM);
        cudaFuncSetAttribute(kC3, cudaFuncAttributeMaxDynamicSharedMemorySize, SMEM_KC);
    }

    // fork: vocab fp16 convert on side stream
    cudaEventRecord(e0, 0);
    cudaStreamWaitEvent(s1, e0, 0);
    kWc<<<2000, 256, 0, s1>>>(vw);
    cudaEventRecord(eW, s1);

    // main chain
    kA1<<<B_, 256>>>(latent, zi);
    kA2<<<B_, 64>>>(latent, zi);
    {
        int cur = 1;
        const float* src = xt;
        for (int it = 0; it < 8; it++) {
            float* dst = (it & 1) ? mp1 : mp0;
            kBD<<<dim3(B_, 4), 256, KBD_SMEM>>>(src, dst, cur, it == 7);
            src = dst;
            cur <<= 1;
        }
    }
    kB2<<<256, 256>>>(latent, zi);

    // fork: exact target logits overlap with kC3
    cudaEventRecord(eZ, 0);
    cudaStreamWaitEvent(s1, eZ, 0);
    kT<<<1024, 256, 0, s1>>>(vw, vb, y);
    cudaEventRecord(eT, s1);

    // join vocab convert, run big fused GEMM
    cudaStreamWaitEvent(0, eW, 0);
    kC3<<<128, 256, SMEM_KC>>>(vb);

    cudaStreamWaitEvent(0, eT, 0);
    kF<<<32, 256>>>(out);
}

// round 8
// speedup vs baseline: 5.5660x; 1.0098x over previous
#include <cuda_runtime.h>
#include <cuda_fp16.h>
#include <math_constants.h>
#include <cstdint>

// ---------------- problem constants ----------------
#define B_     32
#define S_     64
#define E_     128
#define TSTEP  256
#define VOCAB  32000
#define ROWS   8192
#define CPS    125            // chunks (of 128 vocab) per slice; 2 slices
#define L2E    1.4426950408889634f

// ---------------- scratch ----------------
__device__ float g_scores[B_*S_*S_];
__device__ float g_xtran [B_*S_*S_];
__device__ float g_A     [B_*TSTEP*S_];
__device__ float g_zs    [ROWS*E_];
__device__ float g_bl2   [VOCAB];           // bias*L2E + (127 - 30*L2E)
__device__ __align__(16) unsigned short g_w16[VOCAB*E_];
__device__ __align__(16) unsigned short g_z16[ROWS*E_];
__device__ float g_eps[8*ROWS];
__device__ float g_tg [ROWS];

// ---------------- helpers ----------------
__device__ __forceinline__ uint32_t smem_u32b(const void* p) {
    uint32_t a;
    asm("{ .reg .u64 t; cvta.to.shared.u64 t, %1; cvt.u32.u64 %0, t; }" : "=r"(a) : "l"(p));
    return a;
}
__device__ __forceinline__ void cpa16(uint32_t dst, const void* src) {
    asm volatile("cp.async.cg.shared.global [%0], [%1], 16;" :: "r"(dst), "l"(src));
}
#define CP_COMMIT() asm volatile("cp.async.commit_group;" ::: "memory")
#define CP_WAIT1()  asm volatile("cp.async.wait_group 1;" ::: "memory")

__device__ __forceinline__ void ldm_x4(uint32_t addr, uint32_t& r0, uint32_t& r1, uint32_t& r2, uint32_t& r3) {
    asm volatile("ldmatrix.sync.aligned.m8n8.x4.shared.b16 {%0,%1,%2,%3}, [%4];"
        : "=r"(r0), "=r"(r1), "=r"(r2), "=r"(r3) : "r"(addr));
}
__device__ __forceinline__ void ldm_x2(uint32_t addr, uint32_t& r0, uint32_t& r1) {
    asm volatile("ldmatrix.sync.aligned.m8n8.x2.shared.b16 {%0,%1}, [%2];"
        : "=r"(r0), "=r"(r1) : "r"(addr));
}
// fp16-accumulate HMMA (2 result regs)
__device__ __forceinline__ void mma16816h(uint32_t* d, const uint32_t* a, const uint32_t* b) {
    asm volatile("mma.sync.aligned.m16n8k16.row.col.f16.f16.f16.f16 "
        "{%0,%1}, {%2,%3,%4,%5}, {%6,%7}, {%0,%1};"
        : "+r"(d[0]), "+r"(d[1])
        : "r"(a[0]), "r"(a[1]), "r"(a[2]), "r"(a[3]), "r"(b[0]), "r"(b[1]));
}

typedef unsigned long long u64t;
__device__ __forceinline__ u64t pk2(float lo, float hi) {
    u64t r; asm("mov.b64 %0, {%1, %2};" : "=l"(r) : "f"(lo), "f"(hi)); return r;
}
// volatile: pins program order so epilogue interleaves with HMMA issue
__device__ __forceinline__ u64t fma2v(u64t a, u64t b, u64t c) {
    u64t r; asm volatile("fma.rn.f32x2 %0, %1, %2, %3;" : "=l"(r) : "l"(a), "l"(b), "l"(c)); return r;
}
__device__ __forceinline__ u64t h2f2(uint32_t h) {
    __half2 hh = *(__half2*)&h;
    float2 f = __half22float2(hh);
    u64t r; asm("mov.b64 %0, {%1, %2};" : "=l"(r) : "f"(f.x), "f"(f.y));
    return r;
}

struct ExpC {
    u64t L2E2, MG2, NEG1, C4, C3, C2, C1, ONE2;
};
// packed exp(l-30) accumulate; bl2 pre-biased: bias*L2E + (127 - 30*L2E)
__device__ __forceinline__ void expacc2(u64t acc, u64t bl2, const ExpC& K, u64t& rs) {
    u64t y = fma2v(acc, K.L2E2, bl2);
    u64t t = fma2v(y, K.ONE2, K.MG2);        // y + magic
    u64t n = fma2v(K.MG2, K.NEG1, t);        // t - magic
    u64t f = fma2v(n, K.NEG1, y);            // y - n
    u64t p = fma2v(K.C4, f, K.C3);
    p = fma2v(p, f, K.C2);
    p = fma2v(p, f, K.C1);
    p = fma2v(p, f, K.ONE2);
    uint32_t t0, t1;
    asm("mov.b64 {%0, %1}, %2;" : "=r"(t0), "=r"(t1) : "l"(t));
    t0 <<= 23; t1 <<= 23;
    u64t sc; asm("mov.b64 %0, {%1, %2};" : "=l"(sc) : "r"(t0), "r"(t1));
    rs = fma2v(p, sc, rs);
}

// ================= Kernel A1: scores =================
__global__ void kA1(const float* __restrict__ latent, const int* __restrict__ zi) {
    __shared__ float xkS[64 * 129];
    int b = blockIdx.x, tid = threadIdx.x;
    const float* xq = latent + (size_t)zi[(b >> 2)]     * 32768 + (size_t)(b & 3) * 8192;
    const float* xk = latent + (size_t)zi[8 + (b >> 2)] * 32768 + (size_t)(b & 3) * 8192;
    for (int idx = tid; idx < 8192; idx += 256)
        xkS[(idx >> 7) * 129 + (idx & 127)] = __ldg(xk + idx);
    __syncthreads();
    int t = tid & 63, sg = tid >> 6;
    for (int i = 0; i < 16; i++) {
        int s = sg + 4 * i;
        float acc = 0.f;
        const float4* qp = (const float4*)(xq + s * 128);
        #pragma unroll 8
        for (int e4 = 0; e4 < 32; e4++) {
            float4 q = __ldg(qp + e4);
            const float* kp = &xkS[t * 129 + e4 * 4];
            acc += q.x * kp[0] + q.y * kp[1] + q.z * kp[2] + q.w * kp[3];
        }
        g_scores[b * 4096 + s * 64 + t] = acc * 0.08838834764831843f;
    }
}

// ================= Kernel A2: column softmax + att0 (A row 0) =================
__global__ void kA2(const float* __restrict__ latent, const int* __restrict__ zi) {
    int b = blockIdx.x, t = threadIdx.x;
    const float* col = g_scores + b * 4096 + t;
    float mx = -CUDART_INF_F;
    for (int s = 0; s < 64; s++) mx = fmaxf(mx, col[s * 64]);
    float sum = 0.f;
    for (int s = 0; s < 64; s++) {
        float e = __expf(col[s * 64] - mx);
        g_xtran[b * 4096 + s * 64 + t] = e;
        sum += e;
    }
    float inv = 1.f / sum;
    for (int s = 0; s < 64; s++) g_xtran[b * 4096 + s * 64 + t] *= inv;

    const float* ip = latent + (size_t)zi[24 + (b >> 2)] * 32768 + (size_t)(b & 3) * 8192;
    float xi = __ldg(ip + t * 128);
    __shared__ float smv[64];
    smv[t] = xi; __syncthreads();
    float m2 = -CUDART_INF_F;
    for (int s = 0; s < 64; s++) m2 = fmaxf(m2, smv[s]);
    float e2 = __expf(xi - m2);
    __syncthreads(); smv[t] = e2; __syncthreads();
    float su = 0.f;
    for (int s = 0; s < 64; s++) su += smv[s];
    g_A[(size_t)b * 16384 + t] = e2 / su;      // A[0] = att0
}

// ================= Kernel B1v2: single-kernel log-doubling scan =================
// M-column in registers; squaring + extension fused per step; 8 barriers total.
#define KB1_SMEM ((4352*2 + 16384) * 4)
__global__ __launch_bounds__(512) void kB1v2() {
    extern __shared__ float s[];
    float* M0 = s;                 // 64 x 68
    float* M1 = s + 4352;
    float* A  = s + 8704;          // 256 x 64
    int b = blockIdx.x, tid = threadIdx.x;
    int col = tid & 63, rg = tid >> 6;     // rg in 0..7

    for (int i = tid; i < 4096; i += 512)
        M0[(i >> 6) * 68 + (i & 63)] = g_xtran[b * 4096 + i];
    if (tid < 64) A[tid] = g_A[(size_t)b * 16384 + tid];
    __syncthreads();

    float* Mp = M0; float* Mq = M1;
    int cur = 1;
    #pragma unroll 1
    for (int it = 0; it < 8; it++) {
        float mcol[64];
        #pragma unroll
        for (int ss = 0; ss < 64; ss++) mcol[ss] = Mp[ss * 68 + col];
        if (it < 7) {
            #pragma unroll 1
            for (int r = rg; r < 64; r += 8) {
                const float* mr = Mp + r * 68;
                float acc = 0.f;
                #pragma unroll
                for (int ss = 0; ss < 64; ss += 4) {
                    float4 m4 = *(const float4*)&mr[ss];
                    acc += m4.x*mcol[ss] + m4.y*mcol[ss+1] + m4.z*mcol[ss+2] + m4.w*mcol[ss+3];
                }
                Mq[r * 68 + col] = acc;
            }
        }
        #pragma unroll 1
        for (int r = rg; r < cur; r += 8) {
            const float* ar = A + r * 64;
            float acc = 0.f;
            #pragma unroll
            for (int ss = 0; ss < 64; ss += 4) {
                float4 a4 = *(const float4*)&ar[ss];
                acc += a4.x*mcol[ss] + a4.y*mcol[ss+1] + a4.z*mcol[ss+2] + a4.w*mcol[ss+3];
            }
            A[(cur + r) * 64 + col] = acc;
        }
        __syncthreads();
        float* t = Mp; Mp = Mq; Mq = t;
        cur <<= 1;
    }
    for (int i = tid; i < 4096; i += 512) {
        float4 v = *(const float4*)&A[i * 4];
        *(float4*)&g_A[(size_t)b * 16384 + (size_t)i * 4] = v;
    }
}

// ================= Kernel B2: zs = A * xv, + fp16 convert (wide) =================
__global__ __launch_bounds__(256) void kB2(const float* __restrict__ latent, const int* __restrict__ zi) {
    __shared__ float As[2048];
    __shared__ float xvS[8192];
    int b = blockIdx.x >> 3, tb = blockIdx.x & 7;
    int tid = threadIdx.x;
    const float* xv = latent + (size_t)zi[16 + (b >> 2)] * 32768 + (size_t)(b & 3) * 8192;
    for (int i = tid; i < 8192; i += 256) xvS[i] = __ldg(xv + i);
    for (int i = tid; i < 2048; i += 256) As[i] = g_A[(size_t)(b * 256 + tb * 32) * 64 + i];
    __syncthreads();
    int e = tid & 127, h = tid >> 7;
    for (int i = 0; i < 16; i++) {
        int tl = h * 16 + i;
        float acc = 0.f;
        #pragma unroll
        for (int s2 = 0; s2 < 64; s2++) acc += As[tl * 64 + s2] * xvS[s2 * 128 + e];
        size_t row = (size_t)b * 256 + tb * 32 + tl;
        g_zs[row * 128 + e] = acc;
        g_z16[row * 128 + e] = __half_as_ushort(__float2half(acc));
    }
}

// ================= Kernel Wc: vocab_w f32 -> fp16, + bl2 precompute =================
__global__ __launch_bounds__(256) void kWc(const float* __restrict__ vw,
                                           const float* __restrict__ vb) {
    int t = blockIdx.x * 256 + threadIdx.x;
    size_t i = (size_t)t * 8;
    float4 a = *(const float4*)(vw + i);
    float4 b = *(const float4*)(vw + i + 4);
    __half2 h0 = __floats2half2_rn(a.x, a.y);
    __half2 h1 = __floats2half2_rn(a.z, a.w);
    __half2 h2 = __floats2half2_rn(b.x, b.y);
    __half2 h3 = __floats2half2_rn(b.z, b.w);
    uint4 o;
    o.x = *(uint32_t*)&h0; o.y = *(uint32_t*)&h1;
    o.z = *(uint32_t*)&h2; o.w = *(uint32_t*)&h3;
    *(uint4*)(g_w16 + i) = o;
    if (t < VOCAB) g_bl2[t] = fmaf(__ldg(vb + t), L2E, 127.0f - 30.f * L2E);
}

// ================= Kernel T: exact fp32 target logits =================
__global__ __launch_bounds__(256) void kT(const float* __restrict__ vw,
                                          const float* __restrict__ vb,
                                          const int*   __restrict__ y) {
    int r = blockIdx.x * 8 + (threadIdx.x >> 5);
    int lane = threadIdx.x & 31;
    int t = __ldg(y + r);
    float4 z = *(const float4*)(g_zs + (size_t)r * 128 + lane * 4);
    float4 w = *(const float4*)(vw + (size_t)t * 128 + lane * 4);
    float d = z.x * w.x + z.y * w.y + z.z * w.z + z.w * w.w;
    #pragma unroll
    for (int off = 16; off; off >>= 1) d += __shfl_xor_sync(0xffffffffu, d, off);
    if (lane == 0) g_tg[r] = d + __ldg(vb + t);
}

// ================= Kernel C3: pipelined HMMA + interleaved poly-exp =================
#define PITCH   272
#define SM_A    0
#define SM_B0   34816
#define SMEM_KC 104448

// MMA chunk 'new' (B at Bbase -> hdN), epilogue of previous chunk (hdO, bl2c) interleaved.
template<bool DO_EPI>
__device__ __forceinline__ void do_chunk(uint32_t aBase, uint32_t Bbase,
                                         uint32_t (&hdN)[4][4][2],
                                         uint32_t (&hdO)[4][4][2],
                                         const float* __restrict__ bl2c,
                                         int warp_n, int lane,
                                         const ExpC& K, u64t (&RS)[8]) {
    #pragma unroll
    for (int mt = 0; mt < 4; mt++)
        #pragma unroll
        for (int nt = 0; nt < 4; nt++) { hdN[mt][nt][0] = 0u; hdN[mt][nt][1] = 0u; }

    u64t bv[4];
    if (DO_EPI) {
        #pragma unroll
        for (int nt = 0; nt < 4; nt++)
            bv[nt] = *(const u64t*)&bl2c[warp_n * 32 + nt * 8 + (lane & 3) * 2];
    }

    #pragma unroll
    for (int ks = 0; ks < 8; ks++) {
        uint32_t a[4][4], b[4][2];
        #pragma unroll
        for (int mt = 0; mt < 4; mt++)
            ldm_x4(aBase + (uint32_t)(mt * 16) * PITCH + (uint32_t)(ks * 32),
                   a[mt][0], a[mt][1], a[mt][2], a[mt][3]);
        #pragma unroll
        for (int nt = 0; nt < 4; nt++)
            ldm_x2(Bbase + (uint32_t)(nt * 8) * PITCH + (uint32_t)(ks * 32),
                   b[nt][0], b[nt][1]);
        #pragma unroll
        for (int mt = 0; mt < 4; mt++)
            #pragma unroll
            for (int nt = 0; nt < 4; nt++)
                mma16816h(hdN[mt][nt], a[mt], b[nt]);
        if (DO_EPI) {
            // 2 fragments of the OLD chunk per ks (16 total over 8 ks)
            #pragma unroll
            for (int f = ks * 2; f < ks * 2 + 2; f++) {
                int mt = f >> 2, nt = f & 3;
                expacc2(h2f2(hdO[mt][nt][0]), bv[nt], K, RS[mt * 2 + 0]);
                expacc2(h2f2(hdO[mt][nt][1]), bv[nt], K, RS[mt * 2 + 1]);
            }
        }
    }
}

__device__ __forceinline__ void epi_only(uint32_t (&hdO)[4][4][2],
                                         const float* __restrict__ bl2c,
                                         int warp_n, int lane,
                                         const ExpC& K, u64t (&RS)[8]) {
    #pragma unroll
    for (int nt = 0; nt < 4; nt++) {
        u64t bv = *(const u64t*)&bl2c[warp_n * 32 + nt * 8 + (lane & 3) * 2];
        #pragma unroll
        for (int mt = 0; mt < 4; mt++) {
            expacc2(h2f2(hdO[mt][nt][0]), bv, K, RS[mt * 2 + 0]);
            expacc2(h2f2(hdO[mt][nt][1]), bv, K, RS[mt * 2 + 1]);
        }
    }
}

__global__ __launch_bounds__(256, 1) void kC3() {
    extern __shared__ char sm[];
    uint32_t sb = smem_u32b(sm);
    int tid = threadIdx.x, lane = tid & 31, wid = tid >> 5;
    int warp_m = wid >> 2, warp_n = wid & 3;
    int mtile = blockIdx.x & 63, slice = blockIdx.x >> 6;
    int chunk0 = slice * CPS;

    const char* gz = (const char*)g_z16;
    const char* gw = (const char*)g_w16;

    ExpC K;
    K.L2E2 = pk2(L2E, L2E);
    K.MG2  = pk2(12582912.0f, 12582912.0f);
    K.NEG1 = pk2(-1.0f, -1.0f);
    K.C4   = pk2(0.009618129107f, 0.009618129107f);
    K.C3   = pk2(0.055504108664f, 0.055504108664f);
    K.C2   = pk2(0.240226506959f, 0.240226506959f);
    K.C1   = pk2(0.693147180560f, 0.693147180560f);
    K.ONE2 = pk2(1.0f, 1.0f);

    // prologue: A tile + B0 (group0), B1 (group1)
    #pragma unroll
    for (int i = 0; i < 8; i++) {
        int idx = tid + i * 256, row = idx >> 4, part = idx & 15;
        cpa16(sb + SM_A + row * PITCH + part * 16, gz + ((size_t)mtile << 15) + ((size_t)idx << 4));
    }
    #pragma unroll
    for (int i = 0; i < 8; i++) {
        int idx = tid + i * 256, row = idx >> 4, part = idx & 15;
        cpa16(sb + SM_B0 + row * PITCH + part * 16, gw + ((size_t)chunk0 << 15) + ((size_t)idx << 4));
    }
    CP_COMMIT();
    #pragma unroll
    for (int i = 0; i < 8; i++) {
        int idx = tid + i * 256, row = idx >> 4, part = idx & 15;
        cpa16(sb + SM_B0 + 34816 + row * PITCH + part * 16,
              gw + ((size_t)(chunk0 + 1) << 15) + ((size_t)idx << 4));
    }
    CP_COMMIT();

    uint32_t aBase = sb + SM_A + (uint32_t)(warp_m * 64 + (lane & 15)) * PITCH + (uint32_t)(lane >> 4) * 16;
    uint32_t bRowOff = (uint32_t)(warp_n * 32 + (lane & 7)) * PITCH + (uint32_t)((lane >> 3) & 1) * 16;

    uint32_t hdA[4][4][2], hdB[4][4][2];
    u64t RS[8];
    #pragma unroll
    for (int k = 0; k < 8; k++) RS[k] = 0ULL;

    // MMA(0) -> hdA
    CP_WAIT1();
    __syncthreads();
    do_chunk<false>(aBase, sb + SM_B0 + bRowOff, hdA, hdB, g_bl2, warp_n, lane, K, RS);
    __syncthreads();
    // prefetch B2 -> buf0
    if (2 < CPS) {
        #pragma unroll
        for (int i = 0; i < 8; i++) {
            int idx = tid + i * 256, row = idx >> 4, part = idx & 15;
            cpa16(sb + SM_B0 + row * PITCH + part * 16,
                  gw + ((size_t)(chunk0 + 2) << 15) + ((size_t)idx << 4));
        }
    }
    CP_COMMIT();

    #pragma unroll 1
    for (int c = 0; c < CPS; c++) {
        int p = c & 1;
        const float* bl2c = g_bl2 + (size_t)(chunk0 + c) * 128;
        if (c + 1 < CPS) {
            CP_WAIT1();
            __syncthreads();
            uint32_t Bb = sb + SM_B0 + (uint32_t)(p ^ 1) * 34816 + bRowOff;
            if (p == 0) do_chunk<true>(aBase, Bb, hdB, hdA, bl2c, warp_n, lane, K, RS);
            else        do_chunk<true>(aBase, Bb, hdA, hdB, bl2c, warp_n, lane, K, RS);
            __syncthreads();
            if (c + 3 < CPS) {
                #pragma unroll
                for (int i = 0; i < 8; i++) {
                    int idx = tid + i * 256, row = idx >> 4, part = idx & 15;
                    cpa16(sb + SM_B0 + (uint32_t)(p ^ 1) * 34816 + row * PITCH + part * 16,
                          gw + ((size_t)(chunk0 + c + 3) << 15) + ((size_t)idx << 4));
                }
            }
            CP_COMMIT();
        } else {
            if (p == 0) epi_only(hdA, bl2c, warp_n, lane, K, RS);
            else        epi_only(hdB, bl2c, warp_n, lane, K, RS);
        }
    }

    #pragma unroll
    for (int k = 0; k < 8; k++) {
        float lo, hi;
        asm("mov.b64 {%0, %1}, %2;" : "=f"(lo), "=f"(hi) : "l"(RS[k]));
        float s = lo + hi;
        s += __shfl_xor_sync(0xffffffffu, s, 1);
        s += __shfl_xor_sync(0xffffffffu, s, 2);
        if ((lane & 3) == 0) {
            int mt = k >> 1, rp = k & 1;
            int row = mtile * 128 + warp_m * 64 + mt * 16 + (lane >> 2) + rp * 8;
            g_eps[(slice * 4 + warp_n) * ROWS + row] = s;
        }
    }
}

// ================= Kernel F: merge =================
__global__ void kF(float* __restrict__ out) {
    int r = blockIdx.x * 256 + threadIdx.x;
    float se = 0.f;
    #pragma unroll
    for (int s = 0; s < 8; s++) se += g_eps[s * ROWS + r];
    out[r] = g_tg[r] - 30.f - logf(se);
}

// ================= launch =================
extern "C" void kernel_launch(void* const* d_in, const int* in_sizes, int n_in,
                              void* d_out, int out_size) {
    const float* latent = (const float*)d_in[0];
    const float* vw     = (const float*)d_in[1];
    const float* vb     = (const float*)d_in[2];
    const int*   zi     = (const int*)d_in[3];
    const int*   y      = (const int*)d_in[4];
    float* out = (float*)d_out;

    static cudaStream_t s1 = nullptr;
    static cudaEvent_t e0, eW, eZ, eT;
    if (!s1) {
        cudaStreamCreateWithFlags(&s1, cudaStreamNonBlocking);
        cudaEventCreateWithFlags(&e0, cudaEventDisableTiming);
        cudaEventCreateWithFlags(&eW, cudaEventDisableTiming);
        cudaEventCreateWithFlags(&eZ, cudaEventDisableTiming);
        cudaEventCreateWithFlags(&eT, cudaEventDisableTiming);
        cudaFuncSetAttribute(kB1v2, cudaFuncAttributeMaxDynamicSharedMemorySize, KB1_SMEM);
        cudaFuncSetAttribute(kC3, cudaFuncAttributeMaxDynamicSharedMemorySize, SMEM_KC);
    }

    // fork: vocab fp16 convert + bl2 precompute on side stream
    cudaEventRecord(e0, 0);
    cudaStreamWaitEvent(s1, e0, 0);
    kWc<<<2000, 256, 0, s1>>>(vw, vb);
    cudaEventRecord(eW, s1);

    // main chain
    kA1<<<B_, 256>>>(latent, zi);
    kA2<<<B_, 64>>>(latent, zi);
    kB1v2<<<B_, 512, KB1_SMEM>>>();
    kB2<<<256, 256>>>(latent, zi);

    // fork: exact target logits overlap with kC3
    cudaEventRecord(eZ, 0);
    cudaStreamWaitEvent(s1, eZ, 0);
    kT<<<1024, 256, 0, s1>>>(vw, vb, y);
    cudaEventRecord(eT, s1);

    // join vocab convert, run big fused GEMM
    cudaStreamWaitEvent(0, eW, 0);
    kC3<<<128, 256, SMEM_KC>>>();

    cudaStreamWaitEvent(0, eT, 0);
    kF<<<32, 256>>>(out);
}

// round 10
// speedup vs baseline: 5.9608x; 1.0709x over previous
#include <cuda_runtime.h>
#include <cuda_fp16.h>
#include <math_constants.h>
#include <cstdint>

// ---------------- problem constants ----------------
#define B_     32
#define S_     64
#define E_     128
#define TSTEP  256
#define VOCAB  32000
#define ROWS   8192
#define NCHUNK 250            // vocab chunks of 128
#define GRP    10             // chunks per work unit
#define NGRP   25             // units per mtile
#define NUNITS 1600           // 64 mtiles * 25
#define NCTA   148
#define NSLOT  (NGRP*4)       // (group, warp_n) partial slots
#define L2E    1.4426950408889634f

// ---------------- scratch ----------------
__device__ float g_scores[B_*S_*S_];
__device__ float g_xtran [B_*S_*S_];
__device__ float g_A     [B_*TSTEP*S_];
__device__ float g_zs    [ROWS*E_];
__device__ float g_bl2   [VOCAB];                 // bias*L2E + (127 - 30*L2E)
__device__ __align__(16) unsigned short g_w16[VOCAB*E_];
__device__ __align__(16) unsigned short g_z16[ROWS*E_];
__device__ __align__(16) float g_epsG[NSLOT*ROWS]; // per-(group, warp_n, row) partials
__device__ float g_tg [ROWS];

// ---------------- helpers ----------------
__device__ __forceinline__ uint32_t smem_u32b(const void* p) {
    uint32_t a;
    asm("{ .reg .u64 t; cvta.to.shared.u64 t, %1; cvt.u32.u64 %0, t; }" : "=r"(a) : "l"(p));
    return a;
}
__device__ __forceinline__ void cpa16(uint32_t dst, const void* src) {
    asm volatile("cp.async.cg.shared.global [%0], [%1], 16;" :: "r"(dst), "l"(src));
}
#define CP_COMMIT() asm volatile("cp.async.commit_group;" ::: "memory")
#define CP_WAIT1()  asm volatile("cp.async.wait_group 1;" ::: "memory")

__device__ __forceinline__ void ldm_x4(uint32_t addr, uint32_t& r0, uint32_t& r1, uint32_t& r2, uint32_t& r3) {
    asm volatile("ldmatrix.sync.aligned.m8n8.x4.shared.b16 {%0,%1,%2,%3}, [%4];"
        : "=r"(r0), "=r"(r1), "=r"(r2), "=r"(r3) : "r"(addr));
}
__device__ __forceinline__ void ldm_x2(uint32_t addr, uint32_t& r0, uint32_t& r1) {
    asm volatile("ldmatrix.sync.aligned.m8n8.x2.shared.b16 {%0,%1}, [%2];"
        : "=r"(r0), "=r"(r1) : "r"(addr));
}
// fp16-accumulate HMMA (2 result regs)
__device__ __forceinline__ void mma16816h(uint32_t* d, const uint32_t* a, const uint32_t* b) {
    asm volatile("mma.sync.aligned.m16n8k16.row.col.f16.f16.f16.f16 "
        "{%0,%1}, {%2,%3,%4,%5}, {%6,%7}, {%0,%1};"
        : "+r"(d[0]), "+r"(d[1])
        : "r"(a[0]), "r"(a[1]), "r"(a[2]), "r"(a[3]), "r"(b[0]), "r"(b[1]));
}

typedef unsigned long long u64t;
__device__ __forceinline__ u64t pk2(float lo, float hi) {
    u64t r; asm("mov.b64 %0, {%1, %2};" : "=l"(r) : "f"(lo), "f"(hi)); return r;
}
__device__ __forceinline__ u64t fma2v(u64t a, u64t b, u64t c) {
    u64t r; asm volatile("fma.rn.f32x2 %0, %1, %2, %3;" : "=l"(r) : "l"(a), "l"(b), "l"(c)); return r;
}
__device__ __forceinline__ u64t h2f2(uint32_t h) {
    __half2 hh = *(__half2*)&h;
    float2 f = __half22float2(hh);
    u64t r; asm("mov.b64 %0, {%1, %2};" : "=l"(r) : "f"(f.x), "f"(f.y));
    return r;
}

struct ExpC {
    u64t L2E2, MG2, NEG1, C4, C3, C2, C1, ONE2;
};
// packed exp(l-30) accumulate; bl2 pre-biased: bias*L2E + (127 - 30*L2E)
__device__ __forceinline__ void expacc2(u64t acc, u64t bl2, const ExpC& K, u64t& rs) {
    u64t y = fma2v(acc, K.L2E2, bl2);
    u64t t = fma2v(y, K.ONE2, K.MG2);        // y + magic
    u64t n = fma2v(K.MG2, K.NEG1, t);        // t - magic
    u64t f = fma2v(n, K.NEG1, y);            // y - n
    u64t p = fma2v(K.C4, f, K.C3);
    p = fma2v(p, f, K.C2);
    p = fma2v(p, f, K.C1);
    p = fma2v(p, f, K.ONE2);
    uint32_t t0, t1;
    asm("mov.b64 {%0, %1}, %2;" : "=r"(t0), "=r"(t1) : "l"(t));
    t0 <<= 23; t1 <<= 23;
    u64t sc; asm("mov.b64 %0, {%1, %2};" : "=l"(sc) : "r"(t0), "r"(t1));
    rs = fma2v(p, sc, rs);
}

// ================= Kernel A1: scores =================
__global__ void kA1(const float* __restrict__ latent, const int* __restrict__ zi) {
    __shared__ float xkS[64 * 129];
    int b = blockIdx.x, tid = threadIdx.x;
    const float* xq = latent + (size_t)zi[(b >> 2)]     * 32768 + (size_t)(b & 3) * 8192;
    const float* xk = latent + (size_t)zi[8 + (b >> 2)] * 32768 + (size_t)(b & 3) * 8192;
    for (int idx = tid; idx < 8192; idx += 256)
        xkS[(idx >> 7) * 129 + (idx & 127)] = __ldg(xk + idx);
    __syncthreads();
    int t = tid & 63, sg = tid >> 6;
    for (int i = 0; i < 16; i++) {
        int s = sg + 4 * i;
        float a0 = 0.f, a1 = 0.f, a2 = 0.f, a3 = 0.f;
        const float4* qp = (const float4*)(xq + s * 128);
        #pragma unroll 8
        for (int e4 = 0; e4 < 32; e4++) {
            float4 q = __ldg(qp + e4);
            const float* kp = &xkS[t * 129 + e4 * 4];
            a0 = fmaf(q.x, kp[0], a0);
            a1 = fmaf(q.y, kp[1], a1);
            a2 = fmaf(q.z, kp[2], a2);
            a3 = fmaf(q.w, kp[3], a3);
        }
        g_scores[b * 4096 + s * 64 + t] = ((a0 + a1) + (a2 + a3)) * 0.08838834764831843f;
    }
}

// ================= Kernel A2: column softmax + att0 (A row 0) =================
__global__ void kA2(const float* __restrict__ latent, const int* __restrict__ zi) {
    int b = blockIdx.x, t = threadIdx.x;
    const float* col = g_scores + b * 4096 + t;
    float mx = -CUDART_INF_F;
    for (int s = 0; s < 64; s++) mx = fmaxf(mx, col[s * 64]);
    float sum = 0.f;
    for (int s = 0; s < 64; s++) {
        float e = __expf(col[s * 64] - mx);
        g_xtran[b * 4096 + s * 64 + t] = e;
        sum += e;
    }
    float inv = 1.f / sum;
    for (int s = 0; s < 64; s++) g_xtran[b * 4096 + s * 64 + t] *= inv;

    const float* ip = latent + (size_t)zi[24 + (b >> 2)] * 32768 + (size_t)(b & 3) * 8192;
    float xi = __ldg(ip + t * 128);
    __shared__ float smv[64];
    smv[t] = xi; __syncthreads();
    float m2 = -CUDART_INF_F;
    for (int s = 0; s < 64; s++) m2 = fmaxf(m2, smv[s]);
    float e2 = __expf(xi - m2);
    __syncthreads(); smv[t] = e2; __syncthreads();
    float su = 0.f;
    for (int s = 0; s < 64; s++) su += smv[s];
    g_A[(size_t)b * 16384 + t] = e2 / su;      // A[0] = att0
}

// ---- 64-dot with 8 independent accumulator chains (ILP 8) ----
__device__ __forceinline__ float dot64x(const float* __restrict__ row, const float* mcol) {
    float a0=0.f,a1=0.f,a2=0.f,a3=0.f,a4=0.f,a5=0.f,a6=0.f,a7=0.f;
    #pragma unroll
    for (int ss = 0; ss < 64; ss += 8) {
        float4 x = *(const float4*)&row[ss];
        float4 y = *(const float4*)&row[ss + 4];
        a0 = fmaf(x.x, mcol[ss+0], a0);
        a1 = fmaf(x.y, mcol[ss+1], a1);
        a2 = fmaf(x.z, mcol[ss+2], a2);
        a3 = fmaf(x.w, mcol[ss+3], a3);
        a4 = fmaf(y.x, mcol[ss+4], a4);
        a5 = fmaf(y.y, mcol[ss+5], a5);
        a6 = fmaf(y.z, mcol[ss+6], a6);
        a7 = fmaf(y.w, mcol[ss+7], a7);
    }
    return ((a0 + a1) + (a2 + a3)) + ((a4 + a5) + (a6 + a7));
}

// ================= Kernel B1v3: log-doubling scan, multi-accumulator =================
#define KB1_SMEM ((4352*2 + 16384) * 4)
__global__ __launch_bounds__(512) void kB1v3() {
    extern __shared__ float s[];
    float* M0 = s;                 // 64 x 68
    float* M1 = s + 4352;
    float* A  = s + 8704;          // 256 x 64
    int b = blockIdx.x, tid = threadIdx.x;
    int col = tid & 63, rg = tid >> 6;     // rg in 0..7

    for (int i = tid; i < 4096; i += 512)
        M0[(i >> 6) * 68 + (i & 63)] = g_xtran[b * 4096 + i];
    if (tid < 64) A[tid] = g_A[(size_t)b * 16384 + tid];
    __syncthreads();

    float* Mp = M0; float* Mq = M1;
    int cur = 1;
    #pragma unroll 1
    for (int it = 0; it < 8; it++) {
        float mcol[64];
        #pragma unroll
        for (int ss = 0; ss < 64; ss++) mcol[ss] = Mp[ss * 68 + col];
        if (it < 7) {
            #pragma unroll 2
            for (int r = rg; r < 64; r += 8)
                Mq[r * 68 + col] = dot64x(Mp + r * 68, mcol);
        }
        #pragma unroll 2
        for (int r = rg; r < cur; r += 8)
            A[(cur + r) * 64 + col] = dot64x(A + r * 64, mcol);
        __syncthreads();
        float* t = Mp; Mp = Mq; Mq = t;
        cur <<= 1;
    }
    for (int i = tid; i < 4096; i += 512) {
        float4 v = *(const float4*)&A[i * 4];
        *(float4*)&g_A[(size_t)b * 16384 + (size_t)i * 4] = v;
    }
}

// ================= Kernel B2: zs = A * xv, + fp16 convert =================
__global__ __launch_bounds__(256) void kB2(const float* __restrict__ latent, const int* __restrict__ zi) {
    __shared__ float As[2048];
    __shared__ float xvS[8192];
    int b = blockIdx.x >> 3, tb = blockIdx.x & 7;
    int tid = threadIdx.x;
    const float* xv = latent + (size_t)zi[16 + (b >> 2)] * 32768 + (size_t)(b & 3) * 8192;
    for (int i = tid; i < 8192; i += 256) xvS[i] = __ldg(xv + i);
    for (int i = tid; i < 2048; i += 256) As[i] = g_A[(size_t)(b * 256 + tb * 32) * 64 + i];
    __syncthreads();
    int e = tid & 127, h = tid >> 7;
    for (int i = 0; i < 16; i++) {
        int tl = h * 16 + i;
        float a0 = 0.f, a1 = 0.f, a2 = 0.f, a3 = 0.f;
        #pragma unroll
        for (int s2 = 0; s2 < 64; s2 += 4) {
            a0 = fmaf(As[tl * 64 + s2 + 0], xvS[(s2 + 0) * 128 + e], a0);
            a1 = fmaf(As[tl * 64 + s2 + 1], xvS[(s2 + 1) * 128 + e], a1);
            a2 = fmaf(As[tl * 64 + s2 + 2], xvS[(s2 + 2) * 128 + e], a2);
            a3 = fmaf(As[tl * 64 + s2 + 3], xvS[(s2 + 3) * 128 + e], a3);
        }
        float acc = (a0 + a1) + (a2 + a3);
        size_t row = (size_t)b * 256 + tb * 32 + tl;
        g_zs[row * 128 + e] = acc;
        g_z16[row * 128 + e] = __half_as_ushort(__float2half(acc));
    }
}

// ================= Kernel Wc: vocab fp16 + bl2 precompute + g_epsG zero =================
__global__ __launch_bounds__(256) void kWc(const float* __restrict__ vw,
                                           const float* __restrict__ vb) {
    int t = blockIdx.x * 256 + threadIdx.x;
    size_t i = (size_t)t * 8;
    float4 a = *(const float4*)(vw + i);
    float4 b = *(const float4*)(vw + i + 4);
    __half2 h0 = __floats2half2_rn(a.x, a.y);
    __half2 h1 = __floats2half2_rn(a.z, a.w);
    __half2 h2 = __floats2half2_rn(b.x, b.y);
    __half2 h3 = __floats2half2_rn(b.z, b.w);
    uint4 o;
    o.x = *(uint32_t*)&h0; o.y = *(uint32_t*)&h1;
    o.z = *(uint32_t*)&h2; o.w = *(uint32_t*)&h3;
    *(uint4*)(g_w16 + i) = o;
    if (t < VOCAB) g_bl2[t] = fmaf(__ldg(vb + t), L2E, 127.0f - 30.f * L2E);
    if (t < (NSLOT * ROWS) / 4) {
        float4 z = {0.f, 0.f, 0.f, 0.f};
        ((float4*)g_epsG)[t] = z;
    }
}

// ================= Kernel T: exact fp32 target logits =================
__global__ __launch_bounds__(256) void kT(const float* __restrict__ vw,
                                          const float* __restrict__ vb,
                                          const int*   __restrict__ y) {
    int r = blockIdx.x * 8 + (threadIdx.x >> 5);
    int lane = threadIdx.x & 31;
    int t = __ldg(y + r);
    float4 z = *(const float4*)(g_zs + (size_t)r * 128 + lane * 4);
    float4 w = *(const float4*)(vw + (size_t)t * 128 + lane * 4);
    float d = z.x * w.x + z.y * w.y + z.z * w.z + z.w * w.w;
    #pragma unroll
    for (int off = 16; off; off >>= 1) d += __shfl_xor_sync(0xffffffffu, d, off);
    if (lane == 0) g_tg[r] = d + __ldg(vb + t);
}

// ================= Kernel C4: persistent segment-scheduled HMMA + poly-exp ==========
#define PITCH   272
#define SM_A    0
#define SM_B0   34816
#define SMEM_KC 104448

template<bool DO_EPI>
__device__ __forceinline__ void do_chunk(uint32_t aBase, uint32_t Bbase,
                                         uint32_t (&hdN)[4][4][2],
                                         uint32_t (&hdO)[4][4][2],
                                         const float* __restrict__ bl2c,
                                         int warp_n, int lane,
                                         const ExpC& K, u64t (&RS)[8]) {
    #pragma unroll
    for (int mt = 0; mt < 4; mt++)
        #pragma unroll
        for (int nt = 0; nt < 4; nt++) { hdN[mt][nt][0] = 0u; hdN[mt][nt][1] = 0u; }

    u64t bv[4];
    if (DO_EPI) {
        #pragma unroll
        for (int nt = 0; nt < 4; nt++)
            bv[nt] = *(const u64t*)&bl2c[warp_n * 32 + nt * 8 + (lane & 3) * 2];
    }

    #pragma unroll
    for (int ks = 0; ks < 8; ks++) {
        uint32_t a[4][4], b[4][2];
        #pragma unroll
        for (int mt = 0; mt < 4; mt++)
            ldm_x4(aBase + (uint32_t)(mt * 16) * PITCH + (uint32_t)(ks * 32),
                   a[mt][0], a[mt][1], a[mt][2], a[mt][3]);
        #pragma unroll
        for (int nt = 0; nt < 4; nt++)
            ldm_x2(Bbase + (uint32_t)(nt * 8) * PITCH + (uint32_t)(ks * 32),
                   b[nt][0], b[nt][1]);
        #pragma unroll
        for (int mt = 0; mt < 4; mt++)
            #pragma unroll
            for (int nt = 0; nt < 4; nt++)
                mma16816h(hdN[mt][nt], a[mt], b[nt]);
        if (DO_EPI) {
            #pragma unroll
            for (int f = ks * 2; f < ks * 2 + 2; f++) {
                int mt = f >> 2, nt = f & 3;
                expacc2(h2f2(hdO[mt][nt][0]), bv[nt], K, RS[mt * 2 + 0]);
                expacc2(h2f2(hdO[mt][nt][1]), bv[nt], K, RS[mt * 2 + 1]);
            }
        }
    }
}

__device__ __forceinline__ void epi_only(uint32_t (&hdO)[4][4][2],
                                         const float* __restrict__ bl2c,
                                         int warp_n, int lane,
                                         const ExpC& K, u64t (&RS)[8]) {
    #pragma unroll
    for (int nt = 0; nt < 4; nt++) {
        u64t bv = *(const u64t*)&bl2c[warp_n * 32 + nt * 8 + (lane & 3) * 2];
        #pragma unroll
        for (int mt = 0; mt < 4; mt++) {
            expacc2(h2f2(hdO[mt][nt][0]), bv, K, RS[mt * 2 + 0]);
            expacc2(h2f2(hdO[mt][nt][1]), bv, K, RS[mt * 2 + 1]);
        }
    }
}

__global__ __launch_bounds__(256, 1) void kC4() {
    extern __shared__ char sm[];
    uint32_t sb = smem_u32b(sm);
    int tid = threadIdx.x, lane = tid & 31, wid = tid >> 5;
    int warp_m = wid >> 2, warp_n = wid & 3;

    const char* gz = (const char*)g_z16;
    const char* gw = (const char*)g_w16;

    ExpC K;
    K.L2E2 = pk2(L2E, L2E);
    K.MG2  = pk2(12582912.0f, 12582912.0f);
    K.NEG1 = pk2(-1.0f, -1.0f);
    K.C4   = pk2(0.009618129107f, 0.009618129107f);
    K.C3   = pk2(0.055504108664f, 0.055504108664f);
    K.C2   = pk2(0.240226506959f, 0.240226506959f);
    K.C1   = pk2(0.693147180560f, 0.693147180560f);
    K.ONE2 = pk2(1.0f, 1.0f);

    uint32_t aBase = sb + SM_A + (uint32_t)(warp_m * 64 + (lane & 15)) * PITCH + (uint32_t)(lane >> 4) * 16;
    uint32_t bRowOff = (uint32_t)(warp_n * 32 + (lane & 7)) * PITCH + (uint32_t)((lane >> 3) & 1) * 16;

    int cta = blockIdx.x;
    int u0 = (cta * NUNITS) / NCTA;
    int u1 = ((cta + 1) * NUNITS) / NCTA;

    uint32_t hdA[4][4][2], hdB[4][4][2];
    u64t RS[8];

    int u = u0;
    while (u < u1) {
        int mt   = u / NGRP;
        int uend = min(u1, (mt + 1) * NGRP);
        int g0   = u - mt * NGRP;
        int ch0  = g0 * GRP;
        int nch  = (uend - mt * NGRP) * GRP - ch0;

        #pragma unroll
        for (int k = 0; k < 8; k++) RS[k] = 0ULL;

        // segment prologue: A tile + B(ch0) -> group0; B(ch0+1) -> group1
        #pragma unroll
        for (int i = 0; i < 8; i++) {
            int idx = tid + i * 256, row = idx >> 4, part = idx & 15;
            cpa16(sb + SM_A + row * PITCH + part * 16,
                  gz + ((size_t)mt << 15) + ((size_t)idx << 4));
        }
        #pragma unroll
        for (int i = 0; i < 8; i++) {
            int idx = tid + i * 256, row = idx >> 4, part = idx & 15;
            cpa16(sb + SM_B0 + row * PITCH + part * 16,
                  gw + ((size_t)ch0 << 15) + ((size_t)idx << 4));
        }
        CP_COMMIT();
        #pragma unroll
        for (int i = 0; i < 8; i++) {
            int idx = tid + i * 256, row = idx >> 4, part = idx & 15;
            cpa16(sb + SM_B0 + 34816 + row * PITCH + part * 16,
                  gw + ((size_t)(ch0 + 1) << 15) + ((size_t)idx << 4));
        }
        CP_COMMIT();

        CP_WAIT1();
        __syncthreads();
        do_chunk<false>(aBase, sb + SM_B0 + bRowOff, hdA, hdB, g_bl2, warp_n, lane, K, RS);
        __syncthreads();
        if (2 < nch) {
            #pragma unroll
            for (int i = 0; i < 8; i++) {
                int idx = tid + i * 256, row = idx >> 4, part = idx & 15;
                cpa16(sb + SM_B0 + row * PITCH + part * 16,
                      gw + ((size_t)(ch0 + 2) << 15) + ((size_t)idx << 4));
            }
        }
        CP_COMMIT();

        #pragma unroll 1
        for (int c = 0; c < nch; c++) {
            int p = c & 1;
            const float* bl2c = g_bl2 + (size_t)(ch0 + c) * 128;
            if (c + 1 < nch) {
                CP_WAIT1();
                __syncthreads();
                uint32_t Bb = sb + SM_B0 + (uint32_t)(p ^ 1) * 34816 + bRowOff;
                if (p == 0) do_chunk<true>(aBase, Bb, hdB, hdA, bl2c, warp_n, lane, K, RS);
                else        do_chunk<true>(aBase, Bb, hdA, hdB, bl2c, warp_n, lane, K, RS);
                __syncthreads();
                if (c + 3 < nch) {
                    #pragma unroll
                    for (int i = 0; i < 8; i++) {
                        int idx = tid + i * 256, row = idx >> 4, part = idx & 15;
                        cpa16(sb + SM_B0 + (uint32_t)(p ^ 1) * 34816 + row * PITCH + part * 16,
                              gw + ((size_t)(ch0 + c + 3) << 15) + ((size_t)idx << 4));
                    }
                }
                CP_COMMIT();
            } else {
                if (p == 0) epi_only(hdA, bl2c, warp_n, lane, K, RS);
                else        epi_only(hdB, bl2c, warp_n, lane, K, RS);
            }
        }

        // deterministic flush: slot = (g0, warp_n) — warp_n slots are DISTINCT (R9 bug fix)
        #pragma unroll
        for (int k = 0; k < 8; k++) {
            float lo, hi;
            asm("mov.b64 {%0, %1}, %2;" : "=f"(lo), "=f"(hi) : "l"(RS[k]));
            float s = lo + hi;
            s += __shfl_xor_sync(0xffffffffu, s, 1);
            s += __shfl_xor_sync(0xffffffffu, s, 2);
            if ((lane & 3) == 0) {
                int mtt = k >> 1, rp = k & 1;
                int row = mt * 128 + warp_m * 64 + mtt * 16 + (lane >> 2) + rp * 8;
                g_epsG[(size_t)(g0 * 4 + warp_n) * ROWS + row] = s;
            }
        }
        u = uend;
    }
}

// ================= Kernel F: merge =================
__global__ void kF(float* __restrict__ out) {
    int r = blockIdx.x * 256 + threadIdx.x;
    float se = 0.f;
    #pragma unroll 4
    for (int s = 0; s < NSLOT; s++) se += g_epsG[(size_t)s * ROWS + r];
    out[r] = g_tg[r] - 30.f - logf(se);
}

// ================= launch =================
extern "C" void kernel_launch(void* const* d_in, const int* in_sizes, int n_in,
                              void* d_out, int out_size) {
    const float* latent = (const float*)d_in[0];
    const float* vw     = (const float*)d_in[1];
    const float* vb     = (const float*)d_in[2];
    const int*   zi     = (const int*)d_in[3];
    const int*   y      = (const int*)d_in[4];
    float* out = (float*)d_out;

    static cudaStream_t s1 = nullptr;
    static cudaEvent_t e0, eW, eZ, eT;
    if (!s1) {
        cudaStreamCreateWithFlags(&s1, cudaStreamNonBlocking);
        cudaEventCreateWithFlags(&e0, cudaEventDisableTiming);
        cudaEventCreateWithFlags(&eW, cudaEventDisableTiming);
        cudaEventCreateWithFlags(&eZ, cudaEventDisableTiming);
        cudaEventCreateWithFlags(&eT, cudaEventDisableTiming);
        cudaFuncSetAttribute(kB1v3, cudaFuncAttributeMaxDynamicSharedMemorySize, KB1_SMEM);
        cudaFuncSetAttribute(kC4, cudaFuncAttributeMaxDynamicSharedMemorySize, SMEM_KC);
    }

    // fork: vocab fp16 convert + bl2 precompute + eps zero on side stream
    cudaEventRecord(e0, 0);
    cudaStreamWaitEvent(s1, e0, 0);
    kWc<<<2000, 256, 0, s1>>>(vw, vb);
    cudaEventRecord(eW, s1);

    // main chain
    kA1<<<B_, 256>>>(latent, zi);
    kA2<<<B_, 64>>>(latent, zi);
    kB1v3<<<B_, 512, KB1_SMEM>>>();
    kB2<<<256, 256>>>(latent, zi);

    // fork: exact target logits overlap with kC4
    cudaEventRecord(eZ, 0);
    cudaStreamWaitEvent(s1, eZ, 0);
    kT<<<1024, 256, 0, s1>>>(vw, vb, y);
    cudaEventRecord(eT, s1);

    // join vocab convert, run persistent fused GEMM
    cudaStreamWaitEvent(0, eW, 0);
    kC4<<<NCTA, 256, SMEM_KC>>>();

    cudaStreamWaitEvent(0, eT, 0);
    kF<<<32, 256>>>(out);
}